// round 10
// baseline (speedup 1.0000x reference)
#include <cuda_runtime.h>
#include <cstdint>

// Problem constants
#define B_      2
#define L_      2048
#define D_      1024
#define H_      16
#define HD_     64
#define CHUNK_  128
#define M_ROWS  (B_ * L_)          // 4096
#define QKV_N   (3 * D_)           // 3072

// Scratch (device globals — no allocation allowed)
__device__ __align__(16) float g_q[(size_t)B_ * H_ * L_ * HD_];     // [bh][l][perm(d)]
__device__ __align__(16) float g_k[(size_t)B_ * H_ * L_ * HD_];     // [bh][l][perm(d)]
__device__ __align__(16) float g_v[(size_t)B_ * H_ * HD_ * L_];     // [bh][d][l]  (UNpermuted keys)
__device__ __align__(16) float g_ctx[(size_t)B_ * L_ * D_];         // [m][perm(c)]
__device__ __align__(16) float g_xr[(size_t)M_ROWS * D_];           // [m][perm(k)]
__device__ __align__(16) float g_wqkvr[(size_t)QKV_N * D_];         // [n][perm(k)] (transposed)
__device__ __align__(16) float g_woutr[(size_t)D_ * D_];            // [n][perm(k)] (transposed)

// ===========================================================================
// Helpers
// ===========================================================================
__device__ __forceinline__ uint32_t smem_u32(const void* p) {
    uint32_t a;
    asm("{ .reg .u64 t; cvta.to.shared.u64 t, %1; cvt.u32.u64 %0, t; }" : "=r"(a) : "l"(p));
    return a;
}
__device__ __forceinline__ uint32_t f2tf(float x) {
    uint32_t r;
    asm("cvt.rna.tf32.f32 %0, %1;" : "=r"(r) : "f"(x));
    return r;
}
__device__ __forceinline__ float f2tff(float x) { return __uint_as_float(f2tf(x)); }
__device__ __forceinline__ float ex2(float x) {
    float r;
    asm("ex2.approx.ftz.f32 %0, %1;" : "=f"(r) : "f"(x));
    return r;
}

// K-dim permutation: within each 8-group, b -> ((b&3)<<1)|(b>>2)
__device__ __forceinline__ int perm_idx(int i) {
    return (i & ~7) | ((i & 3) << 1) | ((i >> 2) & 1);
}

// m16n8k8 tf32 mma: D = A*B + D  (A row-major, B col-major)
__device__ __forceinline__ void mma8(float* c, const uint32_t* a, const uint32_t* b) {
    asm volatile(
        "mma.sync.aligned.m16n8k8.row.col.f32.tf32.tf32.f32 "
        "{%0,%1,%2,%3}, {%4,%5,%6,%7}, {%8,%9}, {%0,%1,%2,%3};"
        : "+f"(c[0]), "+f"(c[1]), "+f"(c[2]), "+f"(c[3])
        : "r"(a[0]), "r"(a[1]), "r"(a[2]), "r"(a[3]), "r"(b[0]), "r"(b[1]));
}

__device__ __forceinline__ void cp16(uint32_t dst, const void* src) {
    asm volatile("cp.async.cg.shared.global [%0], [%1], 16;" :: "r"(dst), "l"(src));
}
#define CP_COMMIT() asm volatile("cp.async.commit_group;" ::: "memory")
#define CP_WAIT0()  asm volatile("cp.async.wait_group 0;" ::: "memory")
#define CP_WAIT2()  asm volatile("cp.async.wait_group 2;" ::: "memory")

// ===========================================================================
// Prep kernels (unchanged)
// ===========================================================================
__global__ __launch_bounds__(256) void roundperm_kernel(
    const float4* __restrict__ in, float4* __restrict__ out, int n8)
{
    const int i = blockIdx.x * blockDim.x + threadIdx.x;
    if (i < n8) {
        const float4 a = in[2 * i], b = in[2 * i + 1];
        out[2 * i]     = make_float4(f2tff(a.x), f2tff(b.x), f2tff(a.y), f2tff(b.y));
        out[2 * i + 1] = make_float4(f2tff(a.z), f2tff(b.z), f2tff(a.w), f2tff(b.w));
    }
}

__global__ __launch_bounds__(256) void transperm_kernel(
    const float* __restrict__ in, float* __restrict__ out, int K, int N)
{
    __shared__ float tile[32][33];
    const int k0 = blockIdx.y * 32, n0 = blockIdx.x * 32;
    const int tx = threadIdx.x, ty = threadIdx.y;    // 32 x 8
#pragma unroll
    for (int i = 0; i < 4; i++)
        tile[ty + 8 * i][tx] = in[(size_t)(k0 + ty + 8 * i) * N + n0 + tx];
    __syncthreads();
    const int kp = k0 + perm_idx(tx);
#pragma unroll
    for (int i = 0; i < 4; i++)
        out[(size_t)(n0 + ty + 8 * i) * K + kp] = f2tff(tile[tx][ty + 8 * i]);
}

// ===========================================================================
// tf32 mma GEMM: C[M,N] = A[M,K] @ W[K,N] + bias
// A: [M][perm(K)], Bt: [N][perm(K)]. 128x128 CTA tile.
// 4-stage cp.async pipeline, BK=16 per stage -> ONE barrier per chunk and
// loads run 3 chunks ahead. Row stride 24 floats (conflict-free LDS.64).
// ===========================================================================
#define GS2      24
#define G_OPER_B (128 * GS2 * 4)        // 12288 bytes per operand per stage
#define G_STG_B  (2 * G_OPER_B)         // 24576 bytes per stage
#define GEMM_SMEM (4 * G_STG_B)         // 98304 bytes

__device__ __forceinline__ void gemm_prefetch16(
    uint32_t sb, int stg, const float* A, const float* Bt,
    int K, int bm, int bn, int k0, int tid)
{
    const uint32_t a_st = sb + (uint32_t)stg * G_STG_B;
    const uint32_t b_st = a_st + G_OPER_B;
#pragma unroll
    for (int i = 0; i < 2; i++) {
        const int idx = tid + i * 256;       // 0..511
        const int r = idx >> 2, c = idx & 3;
        cp16(a_st + r * (GS2 * 4) + c * 16, A + (size_t)(bm + r) * K + k0 + c * 4);
    }
#pragma unroll
    for (int i = 0; i < 2; i++) {
        const int idx = tid + i * 256;
        const int r = idx >> 2, c = idx & 3;
        cp16(b_st + r * (GS2 * 4) + c * 16, Bt + (size_t)(bn + r) * K + k0 + c * 4);
    }
}

__global__ __launch_bounds__(256, 2) void gemm_mma_kernel(
    const float* __restrict__ A, const float* __restrict__ Bt,
    const float* __restrict__ bias, float* __restrict__ C,
    int M, int N, int K, int qkv_mode)
{
    extern __shared__ __align__(16) char sm[];
    const uint32_t sb = smem_u32(sm);
    const int tid = threadIdx.x, wid = tid >> 5, lane = tid & 31;
    const int g = lane >> 2, tq = lane & 3;
    const int bm = blockIdx.y * 128, bn = blockIdx.x * 128;
    const int wm = (wid >> 2) * 64, wn = (wid & 3) * 32;

    float c[4][4][4];
#pragma unroll
    for (int mt = 0; mt < 4; mt++)
#pragma unroll
        for (int nt = 0; nt < 4; nt++)
#pragma unroll
            for (int i = 0; i < 4; i++) c[mt][nt][i] = 0.f;

    const int KT = K >> 4;      // 16-wide chunks
    gemm_prefetch16(sb, 0, A, Bt, K, bm, bn, 0, tid);  CP_COMMIT();
    gemm_prefetch16(sb, 1, A, Bt, K, bm, bn, 16, tid); CP_COMMIT();
    gemm_prefetch16(sb, 2, A, Bt, K, bm, bn, 32, tid); CP_COMMIT();

    for (int t = 0; t < KT; t++) {
        CP_WAIT2();             // chunk t landed (<=2 younger groups pending)
        __syncthreads();        // also orders: everyone done with chunk t-1
        const int stg = t & 3;
        {
            const float* As = (const float*)(sm + (size_t)stg * G_STG_B);
            const float* Bs = (const float*)(sm + (size_t)stg * G_STG_B + G_OPER_B);
#pragma unroll
            for (int kb = 0; kb < 2; kb++) {
                uint32_t af[4][4], bf[4][2];
#pragma unroll
                for (int mt = 0; mt < 4; mt++) {
                    const float2 lo = *(const float2*)(As + (wm + mt * 16 + g) * GS2 + kb * 8 + tq * 2);
                    const float2 hi = *(const float2*)(As + (wm + mt * 16 + g + 8) * GS2 + kb * 8 + tq * 2);
                    af[mt][0] = __float_as_uint(lo.x);
                    af[mt][1] = __float_as_uint(hi.x);
                    af[mt][2] = __float_as_uint(lo.y);
                    af[mt][3] = __float_as_uint(hi.y);
                }
#pragma unroll
                for (int nt = 0; nt < 4; nt++) {
                    const float2 bb = *(const float2*)(Bs + (wn + nt * 8 + g) * GS2 + kb * 8 + tq * 2);
                    bf[nt][0] = __float_as_uint(bb.x);
                    bf[nt][1] = __float_as_uint(bb.y);
                }
#pragma unroll
                for (int mt = 0; mt < 4; mt++)
#pragma unroll
                    for (int nt = 0; nt < 4; nt++)
                        mma8(c[mt][nt], af[mt], bf[nt]);
            }
        }
        // prefetch chunk t+3 into stage (t+3)&3 (its last reader was chunk
        // t-1, ordered by the barrier above). Commit unconditionally to keep
        // group accounting uniform.
        if (t + 3 < KT)
            gemm_prefetch16(sb, (t + 3) & 3, A, Bt, K, bm, bn, (t + 3) * 16, tid);
        CP_COMMIT();
    }

    // Epilogue: c0:(g,2tq) c1:(g,2tq+1) c2:(g+8,2tq) c3:(g+8,2tq+1)
#pragma unroll
    for (int mt = 0; mt < 4; mt++) {
#pragma unroll
        for (int nt = 0; nt < 4; nt++) {
            const int col = bn + wn + nt * 8 + 2 * tq;
            const float b0 = bias[col], b1 = bias[col + 1];
            const int r0 = bm + wm + mt * 16 + g;
            const int r1 = r0 + 8;
            float v00 = c[mt][nt][0] + b0, v01 = c[mt][nt][1] + b1;
            float v10 = c[mt][nt][2] + b0, v11 = c[mt][nt][3] + b1;
            if (qkv_mode) {
                v00 = f2tff(v00); v01 = f2tff(v01);
                v10 = f2tff(v10); v11 = f2tff(v11);
                const int which = col >> 10;
                const int h  = (col >> 6) & 15;
                const int dd = col & 63;
                const int bh0 = (r0 >> 11) * H_ + h, l0 = r0 & 2047;
                const int bh1 = (r1 >> 11) * H_ + h, l1 = r1 & 2047;
                if (which == 2) {
                    g_v[((size_t)bh0 * HD_ + dd) * L_ + l0]     = v00;
                    g_v[((size_t)bh0 * HD_ + dd + 1) * L_ + l0] = v01;
                    g_v[((size_t)bh1 * HD_ + dd) * L_ + l1]     = v10;
                    g_v[((size_t)bh1 * HD_ + dd + 1) * L_ + l1] = v11;
                } else {
                    float* tgt = (which == 0) ? g_q : g_k;
                    const int pd0 = perm_idx(dd), pd1 = perm_idx(dd + 1);
                    float* d0 = tgt + ((size_t)bh0 * L_ + l0) * HD_;
                    float* d1 = tgt + ((size_t)bh1 * L_ + l1) * HD_;
                    d0[pd0] = v00; d0[pd1] = v01;
                    d1[pd0] = v10; d1[pd1] = v11;
                }
            } else {
                *(float2*)(C + (size_t)r0 * N + col) = make_float2(v00, v01);
                *(float2*)(C + (size_t)r1 * N + col) = make_float2(v10, v11);
            }
        }
    }
}

// ===========================================================================
// Block-causal flash attention (identical to the proven R9 kernel).
// 512-thread CTA = one q-chunk PAIR; K/V double-buffered; one barrier/tile.
// ===========================================================================
#define KS_ 72
#define VS_ 136
#define K_STAGE_B  (128 * KS_ * 4)           // 36864
#define V_STAGE_B  (HD_ * VS_ * 4)           // 34816
#define AT_VOFF    (2 * K_STAGE_B)           // 73728
#define ATTN_SMEM  (AT_VOFF + 2 * V_STAGE_B) // 143360

__device__ __forceinline__ void attn_prefetch_kv(
    uint32_t kdst, uint32_t vdst, const float* ksrc, const float* vsrc, int tid)
{
#pragma unroll
    for (int i = 0; i < 4; i++) {
        const int idx = tid + i * 512;          // 0..2047
        const int r = idx >> 4, c = idx & 15;   // K: 128 rows x 16 chunks
        cp16(kdst + r * (KS_ * 4) + c * 16, ksrc + r * 64 + c * 4);
    }
#pragma unroll
    for (int i = 0; i < 4; i++) {
        const int idx = tid + i * 512;          // 0..2047
        const int r = idx >> 5, c = idx & 31;   // V: 64 d-rows x 32 chunks
        cp16(vdst + r * (VS_ * 4) + c * 16, vsrc + (size_t)r * L_ + c * 4);
    }
}

__global__ __launch_bounds__(512, 1) void attn_mma_kernel(float* __restrict__ ctx)
{
    extern __shared__ __align__(16) char sm[];
    const uint32_t sb = smem_u32(sm);
    const int tid = threadIdx.x, wid = tid >> 5, lane = tid & 31;
    const int g = lane >> 2, tq = lane & 3;
    const int p  = 7 - ((int)blockIdx.x >> 5);
    const int bh = (int)blockIdx.x & 31;
    const int b = bh >> 4, h = bh & 15;
    const size_t head = (size_t)bh * L_ * HD_;
    const int half = wid >> 3;
    const int my_qc = 2 * p + half;
    const int qc_hi = 2 * p + 1;
    const int m0 = (wid & 7) * 16;

    const float QSCALE = 0.125f * 1.4426950408889634f;
    uint32_t qa[8][4];
    {
        const float* qb = g_q + head + (size_t)(my_qc * CHUNK_ + m0) * HD_;
#pragma unroll
        for (int kb = 0; kb < 8; kb++) {
            const float2 lo = *(const float2*)(qb + g * 64 + kb * 8 + tq * 2);
            const float2 hi = *(const float2*)(qb + (g + 8) * 64 + kb * 8 + tq * 2);
            qa[kb][0] = __float_as_uint(lo.x * QSCALE);
            qa[kb][1] = __float_as_uint(hi.x * QSCALE);
            qa[kb][2] = __float_as_uint(lo.y * QSCALE);
            qa[kb][3] = __float_as_uint(hi.y * QSCALE);
        }
    }

    float o[8][4];
#pragma unroll
    for (int nv = 0; nv < 8; nv++)
#pragma unroll
        for (int i = 0; i < 4; i++) o[nv][i] = 0.f;
    float m_lo = -1e30f, m_hi = -1e30f, ls_lo = 0.f, ls_hi = 0.f;

    attn_prefetch_kv(sb, sb + AT_VOFF, g_k + head, g_v + head, tid);
    CP_COMMIT();

    int s = 0;
    for (int kc = 0; kc <= qc_hi; kc++) {
        CP_WAIT0();
        __syncthreads();

        if (kc < qc_hi)
            attn_prefetch_kv(sb + (uint32_t)(s ^ 1) * K_STAGE_B,
                             sb + AT_VOFF + (uint32_t)(s ^ 1) * V_STAGE_B,
                             g_k + head + (size_t)(kc + 1) * CHUNK_ * HD_,
                             g_v + head + (size_t)(kc + 1) * CHUNK_, tid);
        CP_COMMIT();

        if (kc <= my_qc) {
            const float* Ks = (const float*)(sm + (size_t)s * K_STAGE_B);
            const float* Vs = (const float*)(sm + AT_VOFF + (size_t)s * V_STAGE_B);

            float sc[16][4];
#pragma unroll
            for (int nt = 0; nt < 16; nt++) {
                sc[nt][0] = sc[nt][1] = sc[nt][2] = sc[nt][3] = 0.f;
                const float* kp = Ks + (nt * 8 + g) * KS_;
#pragma unroll
                for (int kb = 0; kb < 8; kb++) {
                    const float2 bb = *(const float2*)(kp + kb * 8 + tq * 2);
                    uint32_t bfr[2];
                    bfr[0] = __float_as_uint(bb.x);
                    bfr[1] = __float_as_uint(bb.y);
                    mma8(sc[nt], qa[kb], bfr);
                }
            }

            float smx_lo = -1e30f, smx_hi = -1e30f;
#pragma unroll
            for (int nt = 0; nt < 16; nt++) {
                smx_lo = fmaxf(smx_lo, fmaxf(sc[nt][0], sc[nt][1]));
                smx_hi = fmaxf(smx_hi, fmaxf(sc[nt][2], sc[nt][3]));
            }
            smx_lo = fmaxf(smx_lo, __shfl_xor_sync(0xffffffffu, smx_lo, 1));
            smx_lo = fmaxf(smx_lo, __shfl_xor_sync(0xffffffffu, smx_lo, 2));
            smx_hi = fmaxf(smx_hi, __shfl_xor_sync(0xffffffffu, smx_hi, 1));
            smx_hi = fmaxf(smx_hi, __shfl_xor_sync(0xffffffffu, smx_hi, 2));
            const float mn_lo = fmaxf(m_lo, smx_lo), mn_hi = fmaxf(m_hi, smx_hi);
            const float corr_lo = ex2(m_lo - mn_lo), corr_hi = ex2(m_hi - mn_hi);
            m_lo = mn_lo; m_hi = mn_hi;
            ls_lo *= corr_lo; ls_hi *= corr_hi;

#pragma unroll
            for (int nt = 0; nt < 16; nt++) {
                const float p0 = ex2(sc[nt][0] - mn_lo), p1 = ex2(sc[nt][1] - mn_lo);
                const float p2 = ex2(sc[nt][2] - mn_hi), p3 = ex2(sc[nt][3] - mn_hi);
                ls_lo += p0 + p1; ls_hi += p2 + p3;
                sc[nt][0] = __uint_as_float(f2tf(p0));
                sc[nt][1] = __uint_as_float(f2tf(p1));
                sc[nt][2] = __uint_as_float(f2tf(p2));
                sc[nt][3] = __uint_as_float(f2tf(p3));
            }

#pragma unroll
            for (int nv = 0; nv < 8; nv++) {
                o[nv][0] *= corr_lo; o[nv][1] *= corr_lo;
                o[nv][2] *= corr_hi; o[nv][3] *= corr_hi;
            }

#pragma unroll
            for (int kb = 0; kb < 16; kb++) {
                uint32_t pa[4];
                pa[0] = __float_as_uint(sc[kb][0]);
                pa[1] = __float_as_uint(sc[kb][2]);
                pa[2] = __float_as_uint(sc[kb][1]);
                pa[3] = __float_as_uint(sc[kb][3]);
#pragma unroll
                for (int nv = 0; nv < 8; nv++) {
                    const float2 vv = *(const float2*)(Vs + (nv * 8 + g) * VS_ + kb * 8 + tq * 2);
                    uint32_t vb[2];
                    vb[0] = __float_as_uint(vv.x);
                    vb[1] = __float_as_uint(vv.y);
                    mma8(o[nv], pa, vb);
                }
            }
        }
        s ^= 1;
    }

    ls_lo += __shfl_xor_sync(0xffffffffu, ls_lo, 1);
    ls_lo += __shfl_xor_sync(0xffffffffu, ls_lo, 2);
    ls_hi += __shfl_xor_sync(0xffffffffu, ls_hi, 1);
    ls_hi += __shfl_xor_sync(0xffffffffu, ls_hi, 2);
    const float il = 1.f / ls_lo, ih = 1.f / ls_hi;

    const int r0 = my_qc * CHUNK_ + m0 + g;
#pragma unroll
    for (int nv = 0; nv < 8; nv++) {
        const int col = h * HD_ + nv * 8 + 2 * tq;
        const int p0 = perm_idx(col), p1 = perm_idx(col + 1);
        float* c0 = ctx + ((size_t)b * L_ + r0) * D_;
        float* c1 = ctx + ((size_t)b * L_ + r0 + 8) * D_;
        c0[p0] = f2tff(o[nv][0] * il); c0[p1] = f2tff(o[nv][1] * il);
        c1[p0] = f2tff(o[nv][2] * ih); c1[p1] = f2tff(o[nv][3] * ih);
    }
}

// ---------------------------------------------------------------------------
extern "C" void kernel_launch(void* const* d_in, const int* in_sizes, int n_in,
                              void* d_out, int out_size)
{
    const float* x    = (const float*)d_in[0];
    const float* Wqkv = (const float*)d_in[1];
    const float* bqkv = (const float*)d_in[2];
    const float* Wout = (const float*)d_in[3];
    const float* bout = (const float*)d_in[4];
    float* out = (float*)d_out;

    (void)in_sizes; (void)n_in; (void)out_size;

    cudaFuncSetAttribute(gemm_mma_kernel, cudaFuncAttributeMaxDynamicSharedMemorySize, GEMM_SMEM);
    cudaFuncSetAttribute(attn_mma_kernel, cudaFuncAttributeMaxDynamicSharedMemorySize, ATTN_SMEM);

    float *ctx_ptr, *xr, *wqkvr, *woutr;
    cudaGetSymbolAddress((void**)&ctx_ptr, g_ctx);
    cudaGetSymbolAddress((void**)&xr, g_xr);
    cudaGetSymbolAddress((void**)&wqkvr, g_wqkvr);
    cudaGetSymbolAddress((void**)&woutr, g_woutr);

    // 0. prep: round+permute x; transpose+round+permute weights
    {
        const int n8 = M_ROWS * D_ / 8;
        roundperm_kernel<<<(n8 + 255) / 256, 256>>>((const float4*)x, (float4*)xr, n8);
        dim3 blk(32, 8);
        transperm_kernel<<<dim3(QKV_N / 32, D_ / 32), blk>>>(Wqkv, wqkvr, D_, QKV_N);
        transperm_kernel<<<dim3(D_ / 32, D_ / 32), blk>>>(Wout, woutr, D_, D_);
    }
    // 1. QKV projection + scatter: q/k [bh][l][perm(d)], v [bh][d][l]
    {
        dim3 grid(QKV_N / 128, M_ROWS / 128);   // (24, 32)
        gemm_mma_kernel<<<grid, 256, GEMM_SMEM>>>(xr, wqkvr, bqkv, nullptr,
                                                  M_ROWS, QKV_N, D_, 1);
    }
    // 2. Block-causal attention -> g_ctx (permuted, tf32-rounded)
    {
        attn_mma_kernel<<<8 * 32, 512, ATTN_SMEM>>>(ctx_ptr);
    }
    // 3. Output projection -> d_out
    {
        dim3 grid(D_ / 128, M_ROWS / 128);      // (8, 32)
        gemm_mma_kernel<<<grid, 256, GEMM_SMEM>>>(ctx_ptr, woutr, bout, out,
                                                  M_ROWS, D_, D_, 0);
    }
}

// round 11
// speedup vs baseline: 1.0397x; 1.0397x over previous
#include <cuda_runtime.h>
#include <cstdint>

// Problem constants
#define B_      2
#define L_      2048
#define D_      1024
#define H_      16
#define HD_     64
#define CHUNK_  128
#define M_ROWS  (B_ * L_)          // 4096
#define QKV_N   (3 * D_)           // 3072

// Scratch (device globals — no allocation allowed)
__device__ __align__(16) float g_q[(size_t)B_ * H_ * L_ * HD_];     // [bh][l][perm(d)]
__device__ __align__(16) float g_k[(size_t)B_ * H_ * L_ * HD_];     // [bh][l][perm(d)]
__device__ __align__(16) float g_v[(size_t)B_ * H_ * HD_ * L_];     // [bh][d][l]  (UNpermuted keys)
__device__ __align__(16) float g_ctx[(size_t)B_ * L_ * D_];         // [m][perm(c)]
__device__ __align__(16) float g_xr[(size_t)M_ROWS * D_];           // [m][perm(k)]
__device__ __align__(16) float g_wqkvr[(size_t)QKV_N * D_];         // [n][perm(k)] (transposed)
__device__ __align__(16) float g_woutr[(size_t)D_ * D_];            // [n][perm(k)] (transposed)

// ===========================================================================
// Helpers
// ===========================================================================
__device__ __forceinline__ uint32_t smem_u32(const void* p) {
    uint32_t a;
    asm("{ .reg .u64 t; cvta.to.shared.u64 t, %1; cvt.u32.u64 %0, t; }" : "=r"(a) : "l"(p));
    return a;
}
__device__ __forceinline__ uint32_t f2tf(float x) {
    uint32_t r;
    asm("cvt.rna.tf32.f32 %0, %1;" : "=r"(r) : "f"(x));
    return r;
}
__device__ __forceinline__ float f2tff(float x) { return __uint_as_float(f2tf(x)); }
__device__ __forceinline__ float ex2(float x) {
    float r;
    asm("ex2.approx.ftz.f32 %0, %1;" : "=f"(r) : "f"(x));
    return r;
}

// K-dim permutation: within each 8-group, b -> ((b&3)<<1)|(b>>2)
__device__ __forceinline__ int perm_idx(int i) {
    return (i & ~7) | ((i & 3) << 1) | ((i >> 2) & 1);
}

// m16n8k8 tf32 mma: D = A*B + D  (A row-major, B col-major)
__device__ __forceinline__ void mma8(float* c, const uint32_t* a, const uint32_t* b) {
    asm volatile(
        "mma.sync.aligned.m16n8k8.row.col.f32.tf32.tf32.f32 "
        "{%0,%1,%2,%3}, {%4,%5,%6,%7}, {%8,%9}, {%0,%1,%2,%3};"
        : "+f"(c[0]), "+f"(c[1]), "+f"(c[2]), "+f"(c[3])
        : "r"(a[0]), "r"(a[1]), "r"(a[2]), "r"(a[3]), "r"(b[0]), "r"(b[1]));
}

__device__ __forceinline__ void cp16(uint32_t dst, const void* src) {
    asm volatile("cp.async.cg.shared.global [%0], [%1], 16;" :: "r"(dst), "l"(src));
}
#define CP_COMMIT() asm volatile("cp.async.commit_group;" ::: "memory")
#define CP_WAIT0()  asm volatile("cp.async.wait_group 0;" ::: "memory")
#define CP_WAIT1()  asm volatile("cp.async.wait_group 1;" ::: "memory")

// ===========================================================================
// Prep kernels (unchanged)
// ===========================================================================
__global__ __launch_bounds__(256) void roundperm_kernel(
    const float4* __restrict__ in, float4* __restrict__ out, int n8)
{
    const int i = blockIdx.x * blockDim.x + threadIdx.x;
    if (i < n8) {
        const float4 a = in[2 * i], b = in[2 * i + 1];
        out[2 * i]     = make_float4(f2tff(a.x), f2tff(b.x), f2tff(a.y), f2tff(b.y));
        out[2 * i + 1] = make_float4(f2tff(a.z), f2tff(b.z), f2tff(a.w), f2tff(b.w));
    }
}

__global__ __launch_bounds__(256) void transperm_kernel(
    const float* __restrict__ in, float* __restrict__ out, int K, int N)
{
    __shared__ float tile[32][33];
    const int k0 = blockIdx.y * 32, n0 = blockIdx.x * 32;
    const int tx = threadIdx.x, ty = threadIdx.y;    // 32 x 8
#pragma unroll
    for (int i = 0; i < 4; i++)
        tile[ty + 8 * i][tx] = in[(size_t)(k0 + ty + 8 * i) * N + n0 + tx];
    __syncthreads();
    const int kp = k0 + perm_idx(tx);
#pragma unroll
    for (int i = 0; i < 4; i++)
        out[(size_t)(n0 + ty + 8 * i) * K + kp] = f2tff(tile[tx][ty + 8 * i]);
}

// ===========================================================================
// tf32 mma GEMM: C[M,N] = A[M,K] @ W[K,N] + bias
// A: [M][perm(K)], Bt: [N][perm(K)]. 64x128 CTA tile, 128 threads (4 warps,
// warp tile 64x32), BK=32, 2-stage; 4 CTAs/SM (fine barrier granularity,
// halved tail-wave waste). A smem: stride-40 linear. B smem: exact 128-B
// rows with XOR granule swizzle c^((r&3)<<1) (32-bank coverage for the
// float2 fragment pattern).
// ===========================================================================
#define GSA       40
#define GA_STG_B  (64 * GSA * 4)          // 10240
#define GB_STG_B  (128 * 32 * 4)          // 16384
#define G_STG_B   (GA_STG_B + GB_STG_B)   // 26624
#define GEMM_SMEM (2 * G_STG_B)           // 53248

__device__ __forceinline__ void gemm_prefetch(
    uint32_t sb, int s, const float* A, const float* Bt,
    int K, int bm, int bn, int k0, int tid)
{
    const uint32_t a_st = sb + (uint32_t)s * G_STG_B;
    const uint32_t b_st = a_st + GA_STG_B;
#pragma unroll
    for (int i = 0; i < 4; i++) {
        const int idx = tid + i * 128;       // 0..511 : A 64 rows x 8 granules
        const int r = idx >> 3, c = idx & 7;
        cp16(a_st + r * (GSA * 4) + c * 16, A + (size_t)(bm + r) * K + k0 + c * 4);
    }
#pragma unroll
    for (int i = 0; i < 8; i++) {
        const int idx = tid + i * 128;       // 0..1023 : B 128 rows x 8 granules
        const int r = idx >> 3, c = idx & 7;
        cp16(b_st + r * 128 + ((c ^ ((r & 3) << 1)) << 4),
             Bt + (size_t)(bn + r) * K + k0 + c * 4);
    }
}

__global__ __launch_bounds__(128, 4) void gemm_mma_kernel(
    const float* __restrict__ A, const float* __restrict__ Bt,
    const float* __restrict__ bias, float* __restrict__ C,
    int M, int N, int K, int qkv_mode)
{
    extern __shared__ __align__(16) char sm[];
    const uint32_t sb = smem_u32(sm);
    const int tid = threadIdx.x, wid = tid >> 5, lane = tid & 31;
    const int g = lane >> 2, tq = lane & 3;
    const int bm = blockIdx.y * 64, bn = blockIdx.x * 128;
    const int wn = wid * 32;
    const int gsw = (g & 3) << 1;            // B-granule swizzle for this lane

    float c[4][4][4];
#pragma unroll
    for (int mt = 0; mt < 4; mt++)
#pragma unroll
        for (int nt = 0; nt < 4; nt++)
#pragma unroll
            for (int i = 0; i < 4; i++) c[mt][nt][i] = 0.f;

    const int KT = K >> 5;
    gemm_prefetch(sb, 0, A, Bt, K, bm, bn, 0, tid);  CP_COMMIT();
    gemm_prefetch(sb, 1, A, Bt, K, bm, bn, 32, tid); CP_COMMIT();

    for (int t = 0; t < KT; t++) {
        CP_WAIT1();
        __syncthreads();
        const int s = t & 1;
        {
            const float* As = (const float*)(sm + (size_t)s * G_STG_B);
            const char*  Bs = sm + (size_t)s * G_STG_B + GA_STG_B;
#pragma unroll
            for (int kb = 0; kb < 4; kb++) {
                uint32_t af[4][4], bf[4][2];
#pragma unroll
                for (int mt = 0; mt < 4; mt++) {
                    const float2 lo = *(const float2*)(As + (mt * 16 + g) * GSA + kb * 8 + tq * 2);
                    const float2 hi = *(const float2*)(As + (mt * 16 + g + 8) * GSA + kb * 8 + tq * 2);
                    af[mt][0] = __float_as_uint(lo.x);
                    af[mt][1] = __float_as_uint(hi.x);
                    af[mt][2] = __float_as_uint(lo.y);
                    af[mt][3] = __float_as_uint(hi.y);
                }
#pragma unroll
                for (int nt = 0; nt < 4; nt++) {
                    const int row = wn + nt * 8 + g;
                    const int gr  = (kb * 2 + (tq >> 1)) ^ gsw;
                    const float2 bb = *(const float2*)(Bs + row * 128 + (gr << 4) + (tq & 1) * 8);
                    bf[nt][0] = __float_as_uint(bb.x);
                    bf[nt][1] = __float_as_uint(bb.y);
                }
#pragma unroll
                for (int mt = 0; mt < 4; mt++)
#pragma unroll
                    for (int nt = 0; nt < 4; nt++)
                        mma8(c[mt][nt], af[mt], bf[nt]);
            }
        }
        __syncthreads();
        if (t + 2 < KT)
            gemm_prefetch(sb, s, A, Bt, K, bm, bn, (t + 2) * 32, tid);
        CP_COMMIT();
    }

    // Epilogue: c0:(g,2tq) c1:(g,2tq+1) c2:(g+8,2tq) c3:(g+8,2tq+1)
#pragma unroll
    for (int mt = 0; mt < 4; mt++) {
#pragma unroll
        for (int nt = 0; nt < 4; nt++) {
            const int col = bn + wn + nt * 8 + 2 * tq;
            const float b0 = bias[col], b1 = bias[col + 1];
            const int r0 = bm + mt * 16 + g;
            const int r1 = r0 + 8;
            float v00 = c[mt][nt][0] + b0, v01 = c[mt][nt][1] + b1;
            float v10 = c[mt][nt][2] + b0, v11 = c[mt][nt][3] + b1;
            if (qkv_mode) {
                v00 = f2tff(v00); v01 = f2tff(v01);
                v10 = f2tff(v10); v11 = f2tff(v11);
                const int which = col >> 10;
                const int h  = (col >> 6) & 15;
                const int dd = col & 63;
                const int bh0 = (r0 >> 11) * H_ + h, l0 = r0 & 2047;
                const int bh1 = (r1 >> 11) * H_ + h, l1 = r1 & 2047;
                if (which == 2) {
                    g_v[((size_t)bh0 * HD_ + dd) * L_ + l0]     = v00;
                    g_v[((size_t)bh0 * HD_ + dd + 1) * L_ + l0] = v01;
                    g_v[((size_t)bh1 * HD_ + dd) * L_ + l1]     = v10;
                    g_v[((size_t)bh1 * HD_ + dd + 1) * L_ + l1] = v11;
                } else {
                    float* tgt = (which == 0) ? g_q : g_k;
                    const int pd0 = perm_idx(dd), pd1 = perm_idx(dd + 1);
                    float* d0 = tgt + ((size_t)bh0 * L_ + l0) * HD_;
                    float* d1 = tgt + ((size_t)bh1 * L_ + l1) * HD_;
                    d0[pd0] = v00; d0[pd1] = v01;
                    d1[pd0] = v10; d1[pd1] = v11;
                }
            } else {
                *(float2*)(C + (size_t)r0 * N + col) = make_float2(v00, v01);
                *(float2*)(C + (size_t)r1 * N + col) = make_float2(v10, v11);
            }
        }
    }
}

// ===========================================================================
// Block-causal flash attention (identical to the proven R9 kernel).
// 512-thread CTA = one q-chunk PAIR; K/V double-buffered; one barrier/tile.
// ===========================================================================
#define KS_ 72
#define VS_ 136
#define K_STAGE_B  (128 * KS_ * 4)           // 36864
#define V_STAGE_B  (HD_ * VS_ * 4)           // 34816
#define AT_VOFF    (2 * K_STAGE_B)           // 73728
#define ATTN_SMEM  (AT_VOFF + 2 * V_STAGE_B) // 143360

__device__ __forceinline__ void attn_prefetch_kv(
    uint32_t kdst, uint32_t vdst, const float* ksrc, const float* vsrc, int tid)
{
#pragma unroll
    for (int i = 0; i < 4; i++) {
        const int idx = tid + i * 512;          // 0..2047
        const int r = idx >> 4, c = idx & 15;   // K: 128 rows x 16 chunks
        cp16(kdst + r * (KS_ * 4) + c * 16, ksrc + r * 64 + c * 4);
    }
#pragma unroll
    for (int i = 0; i < 4; i++) {
        const int idx = tid + i * 512;          // 0..2047
        const int r = idx >> 5, c = idx & 31;   // V: 64 d-rows x 32 chunks
        cp16(vdst + r * (VS_ * 4) + c * 16, vsrc + (size_t)r * L_ + c * 4);
    }
}

__global__ __launch_bounds__(512, 1) void attn_mma_kernel(float* __restrict__ ctx)
{
    extern __shared__ __align__(16) char sm[];
    const uint32_t sb = smem_u32(sm);
    const int tid = threadIdx.x, wid = tid >> 5, lane = tid & 31;
    const int g = lane >> 2, tq = lane & 3;
    const int p  = 7 - ((int)blockIdx.x >> 5);
    const int bh = (int)blockIdx.x & 31;
    const int b = bh >> 4, h = bh & 15;
    const size_t head = (size_t)bh * L_ * HD_;
    const int half = wid >> 3;
    const int my_qc = 2 * p + half;
    const int qc_hi = 2 * p + 1;
    const int m0 = (wid & 7) * 16;

    const float QSCALE = 0.125f * 1.4426950408889634f;
    uint32_t qa[8][4];
    {
        const float* qb = g_q + head + (size_t)(my_qc * CHUNK_ + m0) * HD_;
#pragma unroll
        for (int kb = 0; kb < 8; kb++) {
            const float2 lo = *(const float2*)(qb + g * 64 + kb * 8 + tq * 2);
            const float2 hi = *(const float2*)(qb + (g + 8) * 64 + kb * 8 + tq * 2);
            qa[kb][0] = __float_as_uint(lo.x * QSCALE);
            qa[kb][1] = __float_as_uint(hi.x * QSCALE);
            qa[kb][2] = __float_as_uint(lo.y * QSCALE);
            qa[kb][3] = __float_as_uint(hi.y * QSCALE);
        }
    }

    float o[8][4];
#pragma unroll
    for (int nv = 0; nv < 8; nv++)
#pragma unroll
        for (int i = 0; i < 4; i++) o[nv][i] = 0.f;
    float m_lo = -1e30f, m_hi = -1e30f, ls_lo = 0.f, ls_hi = 0.f;

    attn_prefetch_kv(sb, sb + AT_VOFF, g_k + head, g_v + head, tid);
    CP_COMMIT();

    int s = 0;
    for (int kc = 0; kc <= qc_hi; kc++) {
        CP_WAIT0();
        __syncthreads();

        if (kc < qc_hi)
            attn_prefetch_kv(sb + (uint32_t)(s ^ 1) * K_STAGE_B,
                             sb + AT_VOFF + (uint32_t)(s ^ 1) * V_STAGE_B,
                             g_k + head + (size_t)(kc + 1) * CHUNK_ * HD_,
                             g_v + head + (size_t)(kc + 1) * CHUNK_, tid);
        CP_COMMIT();

        if (kc <= my_qc) {
            const float* Ks = (const float*)(sm + (size_t)s * K_STAGE_B);
            const float* Vs = (const float*)(sm + AT_VOFF + (size_t)s * V_STAGE_B);

            float sc[16][4];
#pragma unroll
            for (int nt = 0; nt < 16; nt++) {
                sc[nt][0] = sc[nt][1] = sc[nt][2] = sc[nt][3] = 0.f;
                const float* kp = Ks + (nt * 8 + g) * KS_;
#pragma unroll
                for (int kb = 0; kb < 8; kb++) {
                    const float2 bb = *(const float2*)(kp + kb * 8 + tq * 2);
                    uint32_t bfr[2];
                    bfr[0] = __float_as_uint(bb.x);
                    bfr[1] = __float_as_uint(bb.y);
                    mma8(sc[nt], qa[kb], bfr);
                }
            }

            float smx_lo = -1e30f, smx_hi = -1e30f;
#pragma unroll
            for (int nt = 0; nt < 16; nt++) {
                smx_lo = fmaxf(smx_lo, fmaxf(sc[nt][0], sc[nt][1]));
                smx_hi = fmaxf(smx_hi, fmaxf(sc[nt][2], sc[nt][3]));
            }
            smx_lo = fmaxf(smx_lo, __shfl_xor_sync(0xffffffffu, smx_lo, 1));
            smx_lo = fmaxf(smx_lo, __shfl_xor_sync(0xffffffffu, smx_lo, 2));
            smx_hi = fmaxf(smx_hi, __shfl_xor_sync(0xffffffffu, smx_hi, 1));
            smx_hi = fmaxf(smx_hi, __shfl_xor_sync(0xffffffffu, smx_hi, 2));
            const float mn_lo = fmaxf(m_lo, smx_lo), mn_hi = fmaxf(m_hi, smx_hi);
            const float corr_lo = ex2(m_lo - mn_lo), corr_hi = ex2(m_hi - mn_hi);
            m_lo = mn_lo; m_hi = mn_hi;
            ls_lo *= corr_lo; ls_hi *= corr_hi;

#pragma unroll
            for (int nt = 0; nt < 16; nt++) {
                const float p0 = ex2(sc[nt][0] - mn_lo), p1 = ex2(sc[nt][1] - mn_lo);
                const float p2 = ex2(sc[nt][2] - mn_hi), p3 = ex2(sc[nt][3] - mn_hi);
                ls_lo += p0 + p1; ls_hi += p2 + p3;
                sc[nt][0] = __uint_as_float(f2tf(p0));
                sc[nt][1] = __uint_as_float(f2tf(p1));
                sc[nt][2] = __uint_as_float(f2tf(p2));
                sc[nt][3] = __uint_as_float(f2tf(p3));
            }

#pragma unroll
            for (int nv = 0; nv < 8; nv++) {
                o[nv][0] *= corr_lo; o[nv][1] *= corr_lo;
                o[nv][2] *= corr_hi; o[nv][3] *= corr_hi;
            }

#pragma unroll
            for (int kb = 0; kb < 16; kb++) {
                uint32_t pa[4];
                pa[0] = __float_as_uint(sc[kb][0]);
                pa[1] = __float_as_uint(sc[kb][2]);
                pa[2] = __float_as_uint(sc[kb][1]);
                pa[3] = __float_as_uint(sc[kb][3]);
#pragma unroll
                for (int nv = 0; nv < 8; nv++) {
                    const float2 vv = *(const float2*)(Vs + (nv * 8 + g) * VS_ + kb * 8 + tq * 2);
                    uint32_t vb[2];
                    vb[0] = __float_as_uint(vv.x);
                    vb[1] = __float_as_uint(vv.y);
                    mma8(o[nv], pa, vb);
                }
            }
        }
        s ^= 1;
    }

    ls_lo += __shfl_xor_sync(0xffffffffu, ls_lo, 1);
    ls_lo += __shfl_xor_sync(0xffffffffu, ls_lo, 2);
    ls_hi += __shfl_xor_sync(0xffffffffu, ls_hi, 1);
    ls_hi += __shfl_xor_sync(0xffffffffu, ls_hi, 2);
    const float il = 1.f / ls_lo, ih = 1.f / ls_hi;

    const int r0 = my_qc * CHUNK_ + m0 + g;
#pragma unroll
    for (int nv = 0; nv < 8; nv++) {
        const int col = h * HD_ + nv * 8 + 2 * tq;
        const int p0 = perm_idx(col), p1 = perm_idx(col + 1);
        float* c0 = ctx + ((size_t)b * L_ + r0) * D_;
        float* c1 = ctx + ((size_t)b * L_ + r0 + 8) * D_;
        c0[p0] = f2tff(o[nv][0] * il); c0[p1] = f2tff(o[nv][1] * il);
        c1[p0] = f2tff(o[nv][2] * ih); c1[p1] = f2tff(o[nv][3] * ih);
    }
}

// ---------------------------------------------------------------------------
extern "C" void kernel_launch(void* const* d_in, const int* in_sizes, int n_in,
                              void* d_out, int out_size)
{
    const float* x    = (const float*)d_in[0];
    const float* Wqkv = (const float*)d_in[1];
    const float* bqkv = (const float*)d_in[2];
    const float* Wout = (const float*)d_in[3];
    const float* bout = (const float*)d_in[4];
    float* out = (float*)d_out;

    (void)in_sizes; (void)n_in; (void)out_size;

    cudaFuncSetAttribute(gemm_mma_kernel, cudaFuncAttributeMaxDynamicSharedMemorySize, GEMM_SMEM);
    cudaFuncSetAttribute(attn_mma_kernel, cudaFuncAttributeMaxDynamicSharedMemorySize, ATTN_SMEM);

    float *ctx_ptr, *xr, *wqkvr, *woutr;
    cudaGetSymbolAddress((void**)&ctx_ptr, g_ctx);
    cudaGetSymbolAddress((void**)&xr, g_xr);
    cudaGetSymbolAddress((void**)&wqkvr, g_wqkvr);
    cudaGetSymbolAddress((void**)&woutr, g_woutr);

    // 0. prep: round+permute x; transpose+round+permute weights
    {
        const int n8 = M_ROWS * D_ / 8;
        roundperm_kernel<<<(n8 + 255) / 256, 256>>>((const float4*)x, (float4*)xr, n8);
        dim3 blk(32, 8);
        transperm_kernel<<<dim3(QKV_N / 32, D_ / 32), blk>>>(Wqkv, wqkvr, D_, QKV_N);
        transperm_kernel<<<dim3(D_ / 32, D_ / 32), blk>>>(Wout, woutr, D_, D_);
    }
    // 1. QKV projection + scatter: q/k [bh][l][perm(d)], v [bh][d][l]
    {
        dim3 grid(QKV_N / 128, M_ROWS / 64);    // (24, 64) = 1536 CTAs
        gemm_mma_kernel<<<grid, 128, GEMM_SMEM>>>(xr, wqkvr, bqkv, nullptr,
                                                  M_ROWS, QKV_N, D_, 1);
    }
    // 2. Block-causal attention -> g_ctx (permuted, tf32-rounded)
    {
        attn_mma_kernel<<<8 * 32, 512, ATTN_SMEM>>>(ctx_ptr);
    }
    // 3. Output projection -> d_out
    {
        dim3 grid(D_ / 128, M_ROWS / 64);       // (8, 64) = 512 CTAs
        gemm_mma_kernel<<<grid, 128, GEMM_SMEM>>>(ctx_ptr, woutr, bout, out,
                                                  M_ROWS, D_, D_, 0);
    }
}

// round 12
// speedup vs baseline: 1.1112x; 1.0688x over previous
#include <cuda_runtime.h>
#include <cstdint>

// Problem constants
#define B_      2
#define L_      2048
#define D_      1024
#define H_      16
#define HD_     64
#define CHUNK_  128
#define M_ROWS  (B_ * L_)          // 4096
#define QKV_N   (3 * D_)           // 3072

// Scratch (device globals — no allocation allowed)
__device__ __align__(16) float g_q[(size_t)B_ * H_ * L_ * HD_];     // [bh][l][perm(d)]
__device__ __align__(16) float g_k[(size_t)B_ * H_ * L_ * HD_];     // [bh][l][perm(d)]
__device__ __align__(16) float g_v[(size_t)B_ * H_ * HD_ * L_];     // [bh][d][l]  (UNpermuted keys)
__device__ __align__(16) float g_ctx[(size_t)B_ * L_ * D_];         // [m][perm(c)]
__device__ __align__(16) float g_xr[(size_t)M_ROWS * D_];           // [m][perm(k)]
__device__ __align__(16) float g_wqkvr[(size_t)QKV_N * D_];         // [n][perm(k)] (transposed)
__device__ __align__(16) float g_woutr[(size_t)D_ * D_];            // [n][perm(k)] (transposed)

// ===========================================================================
// Helpers
// ===========================================================================
__device__ __forceinline__ uint32_t smem_u32(const void* p) {
    uint32_t a;
    asm("{ .reg .u64 t; cvta.to.shared.u64 t, %1; cvt.u32.u64 %0, t; }" : "=r"(a) : "l"(p));
    return a;
}
__device__ __forceinline__ uint32_t f2tf(float x) {
    uint32_t r;
    asm("cvt.rna.tf32.f32 %0, %1;" : "=r"(r) : "f"(x));
    return r;
}
__device__ __forceinline__ float f2tff(float x) { return __uint_as_float(f2tf(x)); }
__device__ __forceinline__ float ex2(float x) {
    float r;
    asm("ex2.approx.ftz.f32 %0, %1;" : "=f"(r) : "f"(x));
    return r;
}

// K-dim permutation: within each 8-group, b -> ((b&3)<<1)|(b>>2)
__device__ __forceinline__ int perm_idx(int i) {
    return (i & ~7) | ((i & 3) << 1) | ((i >> 2) & 1);
}

// m16n8k8 tf32 mma: D = A*B + D  (A row-major, B col-major)
__device__ __forceinline__ void mma8(float* c, const uint32_t* a, const uint32_t* b) {
    asm volatile(
        "mma.sync.aligned.m16n8k8.row.col.f32.tf32.tf32.f32 "
        "{%0,%1,%2,%3}, {%4,%5,%6,%7}, {%8,%9}, {%0,%1,%2,%3};"
        : "+f"(c[0]), "+f"(c[1]), "+f"(c[2]), "+f"(c[3])
        : "r"(a[0]), "r"(a[1]), "r"(a[2]), "r"(a[3]), "r"(b[0]), "r"(b[1]));
}

__device__ __forceinline__ void cp16(uint32_t dst, const void* src) {
    asm volatile("cp.async.cg.shared.global [%0], [%1], 16;" :: "r"(dst), "l"(src));
}
#define CP_COMMIT() asm volatile("cp.async.commit_group;" ::: "memory")
#define CP_WAIT0()  asm volatile("cp.async.wait_group 0;" ::: "memory")
#define CP_WAIT1()  asm volatile("cp.async.wait_group 1;" ::: "memory")

// ===========================================================================
// Prep kernels (unchanged)
// ===========================================================================
__global__ __launch_bounds__(256) void roundperm_kernel(
    const float4* __restrict__ in, float4* __restrict__ out, int n8)
{
    const int i = blockIdx.x * blockDim.x + threadIdx.x;
    if (i < n8) {
        const float4 a = in[2 * i], b = in[2 * i + 1];
        out[2 * i]     = make_float4(f2tff(a.x), f2tff(b.x), f2tff(a.y), f2tff(b.y));
        out[2 * i + 1] = make_float4(f2tff(a.z), f2tff(b.z), f2tff(a.w), f2tff(b.w));
    }
}

__global__ __launch_bounds__(256) void transperm_kernel(
    const float* __restrict__ in, float* __restrict__ out, int K, int N)
{
    __shared__ float tile[32][33];
    const int k0 = blockIdx.y * 32, n0 = blockIdx.x * 32;
    const int tx = threadIdx.x, ty = threadIdx.y;    // 32 x 8
#pragma unroll
    for (int i = 0; i < 4; i++)
        tile[ty + 8 * i][tx] = in[(size_t)(k0 + ty + 8 * i) * N + n0 + tx];
    __syncthreads();
    const int kp = k0 + perm_idx(tx);
#pragma unroll
    for (int i = 0; i < 4; i++)
        out[(size_t)(n0 + ty + 8 * i) * K + kp] = f2tff(tile[tx][ty + 8 * i]);
}

// ===========================================================================
// tf32 mma GEMM: C[M,N] = A[M,K] @ W[K,N] + bias
// 64x128 CTA tile, 128 thr, 4 CTAs/SM, BK=32, 2-stage (R11 structure) with
// strength-reduced addressing: 2x-unrolled stage loop (compile-time stage
// parity -> every LDS/cp dst is [reg+imm]) + hoisted B-swizzle offsets
// ((kb^(g&3))<<5, computed once) + incrementing gmem pointers.
// ===========================================================================
#define GSA       40
#define GA_STG_B  (64 * GSA * 4)          // 10240
#define GB_STG_B  (128 * 32 * 4)          // 16384
#define G_STG_B   (GA_STG_B + GB_STG_B)   // 26624
#define GEMM_SMEM (2 * G_STG_B)           // 53248

// One prefetch: lane-base pointers + compile-time stage/loop immediates.
template<int S>
__device__ __forceinline__ void gemm_prefetch(
    uint32_t adst, uint32_t bdst, const char* asrc, const char* bsrc, int koff)
{
#pragma unroll
    for (int i = 0; i < 4; i++)          // A: rows (tid>>3)+16i
        cp16(adst + S * G_STG_B + i * (16 * GSA * 4), asrc + koff + i * (16 * D_ * 4));
#pragma unroll
    for (int i = 0; i < 8; i++)          // B: rows (tid>>3)+16i
        cp16(bdst + S * G_STG_B + i * (16 * 128), bsrc + koff + i * (16 * D_ * 4));
}

// One stage's compute: compile-time stage parity S.
template<int S>
__device__ __forceinline__ void gemm_stage(
    float c[4][4][4], uint32_t abase, uint32_t bbase, const int* xo)
{
#pragma unroll
    for (int kb = 0; kb < 4; kb++) {
        uint32_t af[4][4], bf[4][2];
#pragma unroll
        for (int mt = 0; mt < 4; mt++) {
            float2 lo, hi;
            asm volatile("ld.shared.v2.f32 {%0,%1}, [%2];"
                : "=f"(lo.x), "=f"(lo.y)
                : "r"(abase + S * G_STG_B + mt * (16 * GSA * 4) + kb * 32));
            asm volatile("ld.shared.v2.f32 {%0,%1}, [%2];"
                : "=f"(hi.x), "=f"(hi.y)
                : "r"(abase + S * G_STG_B + mt * (16 * GSA * 4) + 8 * GSA * 4 + kb * 32));
            af[mt][0] = __float_as_uint(lo.x);
            af[mt][1] = __float_as_uint(hi.x);
            af[mt][2] = __float_as_uint(lo.y);
            af[mt][3] = __float_as_uint(hi.y);
        }
        const uint32_t bkb = bbase + (uint32_t)xo[kb];
#pragma unroll
        for (int nt = 0; nt < 4; nt++) {
            float2 bb;
            asm volatile("ld.shared.v2.f32 {%0,%1}, [%2];"
                : "=f"(bb.x), "=f"(bb.y)
                : "r"(bkb + S * G_STG_B + nt * (8 * 128)));
            bf[nt][0] = __float_as_uint(bb.x);
            bf[nt][1] = __float_as_uint(bb.y);
        }
#pragma unroll
        for (int mt = 0; mt < 4; mt++)
#pragma unroll
            for (int nt = 0; nt < 4; nt++)
                mma8(c[mt][nt], af[mt], bf[nt]);
    }
}

__global__ __launch_bounds__(128, 4) void gemm_mma_kernel(
    const float* __restrict__ A, const float* __restrict__ Bt,
    const float* __restrict__ bias, float* __restrict__ C,
    int M, int N, int K, int qkv_mode)
{
    extern __shared__ __align__(16) char sm[];
    const uint32_t sb = smem_u32(sm);
    const int tid = threadIdx.x, wid = tid >> 5, lane = tid & 31;
    const int g = lane >> 2, tq = lane & 3;
    const int bm = blockIdx.y * 64, bn = blockIdx.x * 128;
    const int wn = wid * 32;

    // --- per-lane prefetch bases (loop-invariant) ---
    const int pr = tid >> 3, pc = tid & 7;               // row/granule for cp
    const uint32_t adst = sb + pr * (GSA * 4) + pc * 16;
    const uint32_t bdst = sb + GA_STG_B + pr * 128 +
                          (uint32_t)((pc ^ ((pr & 3) << 1)) << 4);
    const char* asrc = (const char*)(A + (size_t)(bm + pr) * K) + pc * 16;
    const char* bsrc = (const char*)(Bt + (size_t)(bn + pr) * K) + pc * 16;

    // --- per-lane fragment bases ---
    const uint32_t abase = sb + (uint32_t)(g * (GSA * 4) + tq * 8);
    const uint32_t bbase = sb + GA_STG_B + (uint32_t)((wn + g) * 128 +
                           ((tq >> 1) << 4) + (tq & 1) * 8);
    int xo[4];                                           // hoisted B swizzle
#pragma unroll
    for (int kb = 0; kb < 4; kb++) xo[kb] = (kb ^ (g & 3)) << 5;

    float c[4][4][4];
#pragma unroll
    for (int mt = 0; mt < 4; mt++)
#pragma unroll
        for (int nt = 0; nt < 4; nt++)
#pragma unroll
            for (int i = 0; i < 4; i++) c[mt][nt][i] = 0.f;

    const int KT = K >> 5;                               // 32 (K=1024)
    gemm_prefetch<0>(adst, bdst, asrc, bsrc, 0);   CP_COMMIT();
    gemm_prefetch<1>(adst, bdst, asrc, bsrc, 128); CP_COMMIT();

    for (int t = 0; t < KT; t += 2) {
        const int koff2 = (t + 2) * 128;                 // bytes (32 floats)
        // ---- stage 0 ----
        CP_WAIT1();
        __syncthreads();
        gemm_stage<0>(c, abase, bbase, xo);
        __syncthreads();
        if (t + 2 < KT)
            gemm_prefetch<0>(adst, bdst, asrc, bsrc, koff2);
        CP_COMMIT();
        // ---- stage 1 ----
        CP_WAIT1();
        __syncthreads();
        gemm_stage<1>(c, abase, bbase, xo);
        __syncthreads();
        if (t + 3 < KT)
            gemm_prefetch<1>(adst, bdst, asrc, bsrc, koff2 + 128);
        CP_COMMIT();
    }

    // Epilogue: c0:(g,2tq) c1:(g,2tq+1) c2:(g+8,2tq) c3:(g+8,2tq+1)
#pragma unroll
    for (int mt = 0; mt < 4; mt++) {
#pragma unroll
        for (int nt = 0; nt < 4; nt++) {
            const int col = bn + wn + nt * 8 + 2 * tq;
            const float b0 = bias[col], b1 = bias[col + 1];
            const int r0 = bm + mt * 16 + g;
            const int r1 = r0 + 8;
            float v00 = c[mt][nt][0] + b0, v01 = c[mt][nt][1] + b1;
            float v10 = c[mt][nt][2] + b0, v11 = c[mt][nt][3] + b1;
            if (qkv_mode) {
                v00 = f2tff(v00); v01 = f2tff(v01);
                v10 = f2tff(v10); v11 = f2tff(v11);
                const int which = col >> 10;
                const int h  = (col >> 6) & 15;
                const int dd = col & 63;
                const int bh0 = (r0 >> 11) * H_ + h, l0 = r0 & 2047;
                const int bh1 = (r1 >> 11) * H_ + h, l1 = r1 & 2047;
                if (which == 2) {
                    g_v[((size_t)bh0 * HD_ + dd) * L_ + l0]     = v00;
                    g_v[((size_t)bh0 * HD_ + dd + 1) * L_ + l0] = v01;
                    g_v[((size_t)bh1 * HD_ + dd) * L_ + l1]     = v10;
                    g_v[((size_t)bh1 * HD_ + dd + 1) * L_ + l1] = v11;
                } else {
                    float* tgt = (which == 0) ? g_q : g_k;
                    const int pd0 = perm_idx(dd), pd1 = perm_idx(dd + 1);
                    float* d0 = tgt + ((size_t)bh0 * L_ + l0) * HD_;
                    float* d1 = tgt + ((size_t)bh1 * L_ + l1) * HD_;
                    d0[pd0] = v00; d0[pd1] = v01;
                    d1[pd0] = v10; d1[pd1] = v11;
                }
            } else {
                *(float2*)(C + (size_t)r0 * N + col) = make_float2(v00, v01);
                *(float2*)(C + (size_t)r1 * N + col) = make_float2(v10, v11);
            }
        }
    }
}

// ===========================================================================
// Block-causal flash attention (identical to the proven R9/R11 kernel).
// 512-thread CTA = one q-chunk PAIR; K/V double-buffered; one barrier/tile.
// ===========================================================================
#define KS_ 72
#define VS_ 136
#define K_STAGE_B  (128 * KS_ * 4)           // 36864
#define V_STAGE_B  (HD_ * VS_ * 4)           // 34816
#define AT_VOFF    (2 * K_STAGE_B)           // 73728
#define ATTN_SMEM  (AT_VOFF + 2 * V_STAGE_B) // 143360

__device__ __forceinline__ void attn_prefetch_kv(
    uint32_t kdst, uint32_t vdst, const float* ksrc, const float* vsrc, int tid)
{
#pragma unroll
    for (int i = 0; i < 4; i++) {
        const int idx = tid + i * 512;          // 0..2047
        const int r = idx >> 4, c = idx & 15;   // K: 128 rows x 16 chunks
        cp16(kdst + r * (KS_ * 4) + c * 16, ksrc + r * 64 + c * 4);
    }
#pragma unroll
    for (int i = 0; i < 4; i++) {
        const int idx = tid + i * 512;          // 0..2047
        const int r = idx >> 5, c = idx & 31;   // V: 64 d-rows x 32 chunks
        cp16(vdst + r * (VS_ * 4) + c * 16, vsrc + (size_t)r * L_ + c * 4);
    }
}

__global__ __launch_bounds__(512, 1) void attn_mma_kernel(float* __restrict__ ctx)
{
    extern __shared__ __align__(16) char sm[];
    const uint32_t sb = smem_u32(sm);
    const int tid = threadIdx.x, wid = tid >> 5, lane = tid & 31;
    const int g = lane >> 2, tq = lane & 3;
    const int p  = 7 - ((int)blockIdx.x >> 5);
    const int bh = (int)blockIdx.x & 31;
    const int b = bh >> 4, h = bh & 15;
    const size_t head = (size_t)bh * L_ * HD_;
    const int half = wid >> 3;
    const int my_qc = 2 * p + half;
    const int qc_hi = 2 * p + 1;
    const int m0 = (wid & 7) * 16;

    const float QSCALE = 0.125f * 1.4426950408889634f;
    uint32_t qa[8][4];
    {
        const float* qb = g_q + head + (size_t)(my_qc * CHUNK_ + m0) * HD_;
#pragma unroll
        for (int kb = 0; kb < 8; kb++) {
            const float2 lo = *(const float2*)(qb + g * 64 + kb * 8 + tq * 2);
            const float2 hi = *(const float2*)(qb + (g + 8) * 64 + kb * 8 + tq * 2);
            qa[kb][0] = __float_as_uint(lo.x * QSCALE);
            qa[kb][1] = __float_as_uint(hi.x * QSCALE);
            qa[kb][2] = __float_as_uint(lo.y * QSCALE);
            qa[kb][3] = __float_as_uint(hi.y * QSCALE);
        }
    }

    float o[8][4];
#pragma unroll
    for (int nv = 0; nv < 8; nv++)
#pragma unroll
        for (int i = 0; i < 4; i++) o[nv][i] = 0.f;
    float m_lo = -1e30f, m_hi = -1e30f, ls_lo = 0.f, ls_hi = 0.f;

    attn_prefetch_kv(sb, sb + AT_VOFF, g_k + head, g_v + head, tid);
    CP_COMMIT();

    int s = 0;
    for (int kc = 0; kc <= qc_hi; kc++) {
        CP_WAIT0();
        __syncthreads();

        if (kc < qc_hi)
            attn_prefetch_kv(sb + (uint32_t)(s ^ 1) * K_STAGE_B,
                             sb + AT_VOFF + (uint32_t)(s ^ 1) * V_STAGE_B,
                             g_k + head + (size_t)(kc + 1) * CHUNK_ * HD_,
                             g_v + head + (size_t)(kc + 1) * CHUNK_, tid);
        CP_COMMIT();

        if (kc <= my_qc) {
            const float* Ks = (const float*)(sm + (size_t)s * K_STAGE_B);
            const float* Vs = (const float*)(sm + AT_VOFF + (size_t)s * V_STAGE_B);

            float sc[16][4];
#pragma unroll
            for (int nt = 0; nt < 16; nt++) {
                sc[nt][0] = sc[nt][1] = sc[nt][2] = sc[nt][3] = 0.f;
                const float* kp = Ks + (nt * 8 + g) * KS_;
#pragma unroll
                for (int kb = 0; kb < 8; kb++) {
                    const float2 bb = *(const float2*)(kp + kb * 8 + tq * 2);
                    uint32_t bfr[2];
                    bfr[0] = __float_as_uint(bb.x);
                    bfr[1] = __float_as_uint(bb.y);
                    mma8(sc[nt], qa[kb], bfr);
                }
            }

            float smx_lo = -1e30f, smx_hi = -1e30f;
#pragma unroll
            for (int nt = 0; nt < 16; nt++) {
                smx_lo = fmaxf(smx_lo, fmaxf(sc[nt][0], sc[nt][1]));
                smx_hi = fmaxf(smx_hi, fmaxf(sc[nt][2], sc[nt][3]));
            }
            smx_lo = fmaxf(smx_lo, __shfl_xor_sync(0xffffffffu, smx_lo, 1));
            smx_lo = fmaxf(smx_lo, __shfl_xor_sync(0xffffffffu, smx_lo, 2));
            smx_hi = fmaxf(smx_hi, __shfl_xor_sync(0xffffffffu, smx_hi, 1));
            smx_hi = fmaxf(smx_hi, __shfl_xor_sync(0xffffffffu, smx_hi, 2));
            const float mn_lo = fmaxf(m_lo, smx_lo), mn_hi = fmaxf(m_hi, smx_hi);
            const float corr_lo = ex2(m_lo - mn_lo), corr_hi = ex2(m_hi - mn_hi);
            m_lo = mn_lo; m_hi = mn_hi;
            ls_lo *= corr_lo; ls_hi *= corr_hi;

#pragma unroll
            for (int nt = 0; nt < 16; nt++) {
                const float p0 = ex2(sc[nt][0] - mn_lo), p1 = ex2(sc[nt][1] - mn_lo);
                const float p2 = ex2(sc[nt][2] - mn_hi), p3 = ex2(sc[nt][3] - mn_hi);
                ls_lo += p0 + p1; ls_hi += p2 + p3;
                sc[nt][0] = __uint_as_float(f2tf(p0));
                sc[nt][1] = __uint_as_float(f2tf(p1));
                sc[nt][2] = __uint_as_float(f2tf(p2));
                sc[nt][3] = __uint_as_float(f2tf(p3));
            }

#pragma unroll
            for (int nv = 0; nv < 8; nv++) {
                o[nv][0] *= corr_lo; o[nv][1] *= corr_lo;
                o[nv][2] *= corr_hi; o[nv][3] *= corr_hi;
            }

#pragma unroll
            for (int kb = 0; kb < 16; kb++) {
                uint32_t pa[4];
                pa[0] = __float_as_uint(sc[kb][0]);
                pa[1] = __float_as_uint(sc[kb][2]);
                pa[2] = __float_as_uint(sc[kb][1]);
                pa[3] = __float_as_uint(sc[kb][3]);
#pragma unroll
                for (int nv = 0; nv < 8; nv++) {
                    const float2 vv = *(const float2*)(Vs + (nv * 8 + g) * VS_ + kb * 8 + tq * 2);
                    uint32_t vb[2];
                    vb[0] = __float_as_uint(vv.x);
                    vb[1] = __float_as_uint(vv.y);
                    mma8(o[nv], pa, vb);
                }
            }
        }
        s ^= 1;
    }

    ls_lo += __shfl_xor_sync(0xffffffffu, ls_lo, 1);
    ls_lo += __shfl_xor_sync(0xffffffffu, ls_lo, 2);
    ls_hi += __shfl_xor_sync(0xffffffffu, ls_hi, 1);
    ls_hi += __shfl_xor_sync(0xffffffffu, ls_hi, 2);
    const float il = 1.f / ls_lo, ih = 1.f / ls_hi;

    const int r0 = my_qc * CHUNK_ + m0 + g;
#pragma unroll
    for (int nv = 0; nv < 8; nv++) {
        const int col = h * HD_ + nv * 8 + 2 * tq;
        const int p0 = perm_idx(col), p1 = perm_idx(col + 1);
        float* c0 = ctx + ((size_t)b * L_ + r0) * D_;
        float* c1 = ctx + ((size_t)b * L_ + r0 + 8) * D_;
        c0[p0] = f2tff(o[nv][0] * il); c0[p1] = f2tff(o[nv][1] * il);
        c1[p0] = f2tff(o[nv][2] * ih); c1[p1] = f2tff(o[nv][3] * ih);
    }
}

// ---------------------------------------------------------------------------
extern "C" void kernel_launch(void* const* d_in, const int* in_sizes, int n_in,
                              void* d_out, int out_size)
{
    const float* x    = (const float*)d_in[0];
    const float* Wqkv = (const float*)d_in[1];
    const float* bqkv = (const float*)d_in[2];
    const float* Wout = (const float*)d_in[3];
    const float* bout = (const float*)d_in[4];
    float* out = (float*)d_out;

    (void)in_sizes; (void)n_in; (void)out_size;

    cudaFuncSetAttribute(gemm_mma_kernel, cudaFuncAttributeMaxDynamicSharedMemorySize, GEMM_SMEM);
    cudaFuncSetAttribute(attn_mma_kernel, cudaFuncAttributeMaxDynamicSharedMemorySize, ATTN_SMEM);

    float *ctx_ptr, *xr, *wqkvr, *woutr;
    cudaGetSymbolAddress((void**)&ctx_ptr, g_ctx);
    cudaGetSymbolAddress((void**)&xr, g_xr);
    cudaGetSymbolAddress((void**)&wqkvr, g_wqkvr);
    cudaGetSymbolAddress((void**)&woutr, g_woutr);

    // 0. prep: round+permute x; transpose+round+permute weights
    {
        const int n8 = M_ROWS * D_ / 8;
        roundperm_kernel<<<(n8 + 255) / 256, 256>>>((const float4*)x, (float4*)xr, n8);
        dim3 blk(32, 8);
        transperm_kernel<<<dim3(QKV_N / 32, D_ / 32), blk>>>(Wqkv, wqkvr, D_, QKV_N);
        transperm_kernel<<<dim3(D_ / 32, D_ / 32), blk>>>(Wout, woutr, D_, D_);
    }
    // 1. QKV projection + scatter: q/k [bh][l][perm(d)], v [bh][d][l]
    {
        dim3 grid(QKV_N / 128, M_ROWS / 64);    // (24, 64) = 1536 CTAs
        gemm_mma_kernel<<<grid, 128, GEMM_SMEM>>>(xr, wqkvr, bqkv, nullptr,
                                                  M_ROWS, QKV_N, D_, 1);
    }
    // 2. Block-causal attention -> g_ctx (permuted, tf32-rounded)
    {
        attn_mma_kernel<<<8 * 32, 512, ATTN_SMEM>>>(ctx_ptr);
    }
    // 3. Output projection -> d_out
    {
        dim3 grid(D_ / 128, M_ROWS / 64);       // (8, 64) = 512 CTAs
        gemm_mma_kernel<<<grid, 128, GEMM_SMEM>>>(ctx_ptr, woutr, bout, out,
                                                  M_ROWS, D_, D_, 0);
    }
}

// round 13
// speedup vs baseline: 1.1942x; 1.0747x over previous
#include <cuda_runtime.h>
#include <cstdint>

// Problem constants
#define B_      2
#define L_      2048
#define D_      1024
#define H_      16
#define HD_     64
#define CHUNK_  128
#define M_ROWS  (B_ * L_)          // 4096
#define QKV_N   (3 * D_)           // 3072

// Scratch (device globals — no allocation allowed)
__device__ __align__(16) float g_q[(size_t)B_ * H_ * L_ * HD_];     // [bh][l][perm(d)]
__device__ __align__(16) float g_k[(size_t)B_ * H_ * L_ * HD_];     // [bh][l][perm(d)]
__device__ __align__(16) float g_v[(size_t)B_ * H_ * HD_ * L_];     // [bh][d][l]  (UNpermuted keys)
__device__ __align__(16) float g_ctx[(size_t)B_ * L_ * D_];         // [m][perm(c)]
__device__ __align__(16) float g_xr[(size_t)M_ROWS * D_];           // [m][perm(k)]
__device__ __align__(16) float g_wqkvr[(size_t)QKV_N * D_];         // [n][perm(k)] (transposed)
__device__ __align__(16) float g_woutr[(size_t)D_ * D_];            // [n][perm(k)] (transposed)

// ===========================================================================
// Helpers
// ===========================================================================
__device__ __forceinline__ uint32_t smem_u32(const void* p) {
    uint32_t a;
    asm("{ .reg .u64 t; cvta.to.shared.u64 t, %1; cvt.u32.u64 %0, t; }" : "=r"(a) : "l"(p));
    return a;
}
__device__ __forceinline__ uint32_t f2tf(float x) {
    uint32_t r;
    asm("cvt.rna.tf32.f32 %0, %1;" : "=r"(r) : "f"(x));
    return r;
}
__device__ __forceinline__ float f2tff(float x) { return __uint_as_float(f2tf(x)); }
__device__ __forceinline__ float ex2(float x) {
    float r;
    asm("ex2.approx.ftz.f32 %0, %1;" : "=f"(r) : "f"(x));
    return r;
}

// K-dim permutation: within each 8-group, b -> ((b&3)<<1)|(b>>2)
__device__ __forceinline__ int perm_idx(int i) {
    return (i & ~7) | ((i & 3) << 1) | ((i >> 2) & 1);
}

// m16n8k8 tf32 mma: D = A*B + D  (A row-major, B col-major)
__device__ __forceinline__ void mma8(float* c, const uint32_t* a, const uint32_t* b) {
    asm volatile(
        "mma.sync.aligned.m16n8k8.row.col.f32.tf32.tf32.f32 "
        "{%0,%1,%2,%3}, {%4,%5,%6,%7}, {%8,%9}, {%0,%1,%2,%3};"
        : "+f"(c[0]), "+f"(c[1]), "+f"(c[2]), "+f"(c[3])
        : "r"(a[0]), "r"(a[1]), "r"(a[2]), "r"(a[3]), "r"(b[0]), "r"(b[1]));
}

__device__ __forceinline__ void cp16(uint32_t dst, const void* src) {
    asm volatile("cp.async.cg.shared.global [%0], [%1], 16;" :: "r"(dst), "l"(src));
}
#define CP_COMMIT() asm volatile("cp.async.commit_group;" ::: "memory")
#define CP_WAIT0()  asm volatile("cp.async.wait_group 0;" ::: "memory")
#define CP_WAIT1()  asm volatile("cp.async.wait_group 1;" ::: "memory")

// ===========================================================================
// Prep kernels (unchanged)
// ===========================================================================
__global__ __launch_bounds__(256) void roundperm_kernel(
    const float4* __restrict__ in, float4* __restrict__ out, int n8)
{
    const int i = blockIdx.x * blockDim.x + threadIdx.x;
    if (i < n8) {
        const float4 a = in[2 * i], b = in[2 * i + 1];
        out[2 * i]     = make_float4(f2tff(a.x), f2tff(b.x), f2tff(a.y), f2tff(b.y));
        out[2 * i + 1] = make_float4(f2tff(a.z), f2tff(b.z), f2tff(a.w), f2tff(b.w));
    }
}

__global__ __launch_bounds__(256) void transperm_kernel(
    const float* __restrict__ in, float* __restrict__ out, int K, int N)
{
    __shared__ float tile[32][33];
    const int k0 = blockIdx.y * 32, n0 = blockIdx.x * 32;
    const int tx = threadIdx.x, ty = threadIdx.y;    // 32 x 8
#pragma unroll
    for (int i = 0; i < 4; i++)
        tile[ty + 8 * i][tx] = in[(size_t)(k0 + ty + 8 * i) * N + n0 + tx];
    __syncthreads();
    const int kp = k0 + perm_idx(tx);
#pragma unroll
    for (int i = 0; i < 4; i++)
        out[(size_t)(n0 + ty + 8 * i) * K + kp] = f2tff(tile[tx][ty + 8 * i]);
}

// ===========================================================================
// tf32 mma GEMM (byte-identical to the proven R12 kernel)
// ===========================================================================
#define GSA       40
#define GA_STG_B  (64 * GSA * 4)          // 10240
#define GB_STG_B  (128 * 32 * 4)          // 16384
#define G_STG_B   (GA_STG_B + GB_STG_B)   // 26624
#define GEMM_SMEM (2 * G_STG_B)           // 53248

template<int S>
__device__ __forceinline__ void gemm_prefetch(
    uint32_t adst, uint32_t bdst, const char* asrc, const char* bsrc, int koff)
{
#pragma unroll
    for (int i = 0; i < 4; i++)
        cp16(adst + S * G_STG_B + i * (16 * GSA * 4), asrc + koff + i * (16 * D_ * 4));
#pragma unroll
    for (int i = 0; i < 8; i++)
        cp16(bdst + S * G_STG_B + i * (16 * 128), bsrc + koff + i * (16 * D_ * 4));
}

template<int S>
__device__ __forceinline__ void gemm_stage(
    float c[4][4][4], uint32_t abase, uint32_t bbase, const int* xo)
{
#pragma unroll
    for (int kb = 0; kb < 4; kb++) {
        uint32_t af[4][4], bf[4][2];
#pragma unroll
        for (int mt = 0; mt < 4; mt++) {
            float2 lo, hi;
            asm volatile("ld.shared.v2.f32 {%0,%1}, [%2];"
                : "=f"(lo.x), "=f"(lo.y)
                : "r"(abase + S * G_STG_B + mt * (16 * GSA * 4) + kb * 32));
            asm volatile("ld.shared.v2.f32 {%0,%1}, [%2];"
                : "=f"(hi.x), "=f"(hi.y)
                : "r"(abase + S * G_STG_B + mt * (16 * GSA * 4) + 8 * GSA * 4 + kb * 32));
            af[mt][0] = __float_as_uint(lo.x);
            af[mt][1] = __float_as_uint(hi.x);
            af[mt][2] = __float_as_uint(lo.y);
            af[mt][3] = __float_as_uint(hi.y);
        }
        const uint32_t bkb = bbase + (uint32_t)xo[kb];
#pragma unroll
        for (int nt = 0; nt < 4; nt++) {
            float2 bb;
            asm volatile("ld.shared.v2.f32 {%0,%1}, [%2];"
                : "=f"(bb.x), "=f"(bb.y)
                : "r"(bkb + S * G_STG_B + nt * (8 * 128)));
            bf[nt][0] = __float_as_uint(bb.x);
            bf[nt][1] = __float_as_uint(bb.y);
        }
#pragma unroll
        for (int mt = 0; mt < 4; mt++)
#pragma unroll
            for (int nt = 0; nt < 4; nt++)
                mma8(c[mt][nt], af[mt], bf[nt]);
    }
}

__global__ __launch_bounds__(128, 4) void gemm_mma_kernel(
    const float* __restrict__ A, const float* __restrict__ Bt,
    const float* __restrict__ bias, float* __restrict__ C,
    int M, int N, int K, int qkv_mode)
{
    extern __shared__ __align__(16) char sm[];
    const uint32_t sb = smem_u32(sm);
    const int tid = threadIdx.x, wid = tid >> 5, lane = tid & 31;
    const int g = lane >> 2, tq = lane & 3;
    const int bm = blockIdx.y * 64, bn = blockIdx.x * 128;
    const int wn = wid * 32;

    const int pr = tid >> 3, pc = tid & 7;
    const uint32_t adst = sb + pr * (GSA * 4) + pc * 16;
    const uint32_t bdst = sb + GA_STG_B + pr * 128 +
                          (uint32_t)((pc ^ ((pr & 3) << 1)) << 4);
    const char* asrc = (const char*)(A + (size_t)(bm + pr) * K) + pc * 16;
    const char* bsrc = (const char*)(Bt + (size_t)(bn + pr) * K) + pc * 16;

    const uint32_t abase = sb + (uint32_t)(g * (GSA * 4) + tq * 8);
    const uint32_t bbase = sb + GA_STG_B + (uint32_t)((wn + g) * 128 +
                           ((tq >> 1) << 4) + (tq & 1) * 8);
    int xo[4];
#pragma unroll
    for (int kb = 0; kb < 4; kb++) xo[kb] = (kb ^ (g & 3)) << 5;

    float c[4][4][4];
#pragma unroll
    for (int mt = 0; mt < 4; mt++)
#pragma unroll
        for (int nt = 0; nt < 4; nt++)
#pragma unroll
            for (int i = 0; i < 4; i++) c[mt][nt][i] = 0.f;

    const int KT = K >> 5;
    gemm_prefetch<0>(adst, bdst, asrc, bsrc, 0);   CP_COMMIT();
    gemm_prefetch<1>(adst, bdst, asrc, bsrc, 128); CP_COMMIT();

    for (int t = 0; t < KT; t += 2) {
        const int koff2 = (t + 2) * 128;
        CP_WAIT1();
        __syncthreads();
        gemm_stage<0>(c, abase, bbase, xo);
        __syncthreads();
        if (t + 2 < KT)
            gemm_prefetch<0>(adst, bdst, asrc, bsrc, koff2);
        CP_COMMIT();
        CP_WAIT1();
        __syncthreads();
        gemm_stage<1>(c, abase, bbase, xo);
        __syncthreads();
        if (t + 3 < KT)
            gemm_prefetch<1>(adst, bdst, asrc, bsrc, koff2 + 128);
        CP_COMMIT();
    }

#pragma unroll
    for (int mt = 0; mt < 4; mt++) {
#pragma unroll
        for (int nt = 0; nt < 4; nt++) {
            const int col = bn + wn + nt * 8 + 2 * tq;
            const float b0 = bias[col], b1 = bias[col + 1];
            const int r0 = bm + mt * 16 + g;
            const int r1 = r0 + 8;
            float v00 = c[mt][nt][0] + b0, v01 = c[mt][nt][1] + b1;
            float v10 = c[mt][nt][2] + b0, v11 = c[mt][nt][3] + b1;
            if (qkv_mode) {
                v00 = f2tff(v00); v01 = f2tff(v01);
                v10 = f2tff(v10); v11 = f2tff(v11);
                const int which = col >> 10;
                const int h  = (col >> 6) & 15;
                const int dd = col & 63;
                const int bh0 = (r0 >> 11) * H_ + h, l0 = r0 & 2047;
                const int bh1 = (r1 >> 11) * H_ + h, l1 = r1 & 2047;
                if (which == 2) {
                    g_v[((size_t)bh0 * HD_ + dd) * L_ + l0]     = v00;
                    g_v[((size_t)bh0 * HD_ + dd + 1) * L_ + l0] = v01;
                    g_v[((size_t)bh1 * HD_ + dd) * L_ + l1]     = v10;
                    g_v[((size_t)bh1 * HD_ + dd + 1) * L_ + l1] = v11;
                } else {
                    float* tgt = (which == 0) ? g_q : g_k;
                    const int pd0 = perm_idx(dd), pd1 = perm_idx(dd + 1);
                    float* d0 = tgt + ((size_t)bh0 * L_ + l0) * HD_;
                    float* d1 = tgt + ((size_t)bh1 * L_ + l1) * HD_;
                    d0[pd0] = v00; d0[pd1] = v01;
                    d1[pd0] = v10; d1[pd1] = v11;
                }
            } else {
                *(float2*)(C + (size_t)r0 * N + col) = make_float2(v00, v01);
                *(float2*)(C + (size_t)r1 * N + col) = make_float2(v10, v11);
            }
        }
    }
}

// ===========================================================================
// Block-causal flash attention v2: 256 threads (8 warps), warp tile m32.
// Warps 0-3 -> chunk 2p, warps 4-7 -> chunk 2p+1. Each warp owns 32 q-rows
// (two m16 sub-tiles) sharing every K/V fragment -> smem-read bytes halved.
// Keys processed in two 64-key halves per tile (extra online-softmax step).
// K/V double-buffered; one barrier per tile.
// ===========================================================================
#define KS_ 72
#define VS_ 136
#define K_STAGE_B  (128 * KS_ * 4)           // 36864
#define V_STAGE_B  (HD_ * VS_ * 4)           // 34816
#define AT_VOFF    (2 * K_STAGE_B)           // 73728
#define ATTN_SMEM  (AT_VOFF + 2 * V_STAGE_B) // 143360

__device__ __forceinline__ void attn_prefetch_kv(
    uint32_t kdst, uint32_t vdst, const float* ksrc, const float* vsrc, int tid)
{
#pragma unroll
    for (int i = 0; i < 8; i++) {
        const int idx = tid + i * 256;          // 0..2047
        const int r = idx >> 4, c = idx & 15;   // K: 128 rows x 16 chunks
        cp16(kdst + r * (KS_ * 4) + c * 16, ksrc + r * 64 + c * 4);
    }
#pragma unroll
    for (int i = 0; i < 8; i++) {
        const int idx = tid + i * 256;          // 0..2047
        const int r = idx >> 5, c = idx & 31;   // V: 64 d-rows x 32 chunks
        cp16(vdst + r * (VS_ * 4) + c * 16, vsrc + (size_t)r * L_ + c * 4);
    }
}

__global__ __launch_bounds__(256, 1) void attn_mma_kernel(float* __restrict__ ctx)
{
    extern __shared__ __align__(16) char sm[];
    const uint32_t sb = smem_u32(sm);
    const int tid = threadIdx.x, wid = tid >> 5, lane = tid & 31;
    const int g = lane >> 2, tq = lane & 3;
    const int p  = 7 - ((int)blockIdx.x >> 5);
    const int bh = (int)blockIdx.x & 31;
    const int b = bh >> 4, h = bh & 15;
    const size_t head = (size_t)bh * L_ * HD_;
    const int half = wid >> 2;                  // 0: chunk 2p, 1: chunk 2p+1
    const int my_qc = 2 * p + half;
    const int qc_hi = 2 * p + 1;
    const int wr0 = (wid & 3) * 32;             // warp's first q-row in chunk

    // Q fragments for both m16 sub-tiles; fold 1/8 * log2(e)
    const float QSCALE = 0.125f * 1.4426950408889634f;
    uint32_t qa[2][8][4];
#pragma unroll
    for (int mt2 = 0; mt2 < 2; mt2++) {
        const float* qb = g_q + head + (size_t)(my_qc * CHUNK_ + wr0 + mt2 * 16) * HD_;
#pragma unroll
        for (int kb = 0; kb < 8; kb++) {
            const float2 lo = *(const float2*)(qb + g * 64 + kb * 8 + tq * 2);
            const float2 hi = *(const float2*)(qb + (g + 8) * 64 + kb * 8 + tq * 2);
            qa[mt2][kb][0] = __float_as_uint(lo.x * QSCALE);
            qa[mt2][kb][1] = __float_as_uint(hi.x * QSCALE);
            qa[mt2][kb][2] = __float_as_uint(lo.y * QSCALE);
            qa[mt2][kb][3] = __float_as_uint(hi.y * QSCALE);
        }
    }

    float o[2][8][4];
#pragma unroll
    for (int mt2 = 0; mt2 < 2; mt2++)
#pragma unroll
        for (int nv = 0; nv < 8; nv++)
#pragma unroll
            for (int i = 0; i < 4; i++) o[mt2][nv][i] = 0.f;
    float mr[2][2] = {{-1e30f, -1e30f}, {-1e30f, -1e30f}};   // [mt2][lo/hi]
    float ls[2][2] = {{0.f, 0.f}, {0.f, 0.f}};

    attn_prefetch_kv(sb, sb + AT_VOFF, g_k + head, g_v + head, tid);
    CP_COMMIT();

    int s = 0;
    for (int kc = 0; kc <= qc_hi; kc++) {
        CP_WAIT0();
        __syncthreads();   // KV(kc) visible; everyone done reading old buffers

        if (kc < qc_hi)
            attn_prefetch_kv(sb + (uint32_t)(s ^ 1) * K_STAGE_B,
                             sb + AT_VOFF + (uint32_t)(s ^ 1) * V_STAGE_B,
                             g_k + head + (size_t)(kc + 1) * CHUNK_ * HD_,
                             g_v + head + (size_t)(kc + 1) * CHUNK_, tid);
        CP_COMMIT();

        if (kc <= my_qc) {
            const float* Ks = (const float*)(sm + (size_t)s * K_STAGE_B);
            const float* Vs = (const float*)(sm + AT_VOFF + (size_t)s * V_STAGE_B);

#pragma unroll
            for (int hk = 0; hk < 2; hk++) {     // 64-key halves
                // S = Q K^T (m32 x n64, k64): one K frag feeds 2 mma
                float sc[2][8][4];
#pragma unroll
                for (int nt = 0; nt < 8; nt++) {
                    sc[0][nt][0] = sc[0][nt][1] = sc[0][nt][2] = sc[0][nt][3] = 0.f;
                    sc[1][nt][0] = sc[1][nt][1] = sc[1][nt][2] = sc[1][nt][3] = 0.f;
                    const float* kp = Ks + (hk * 64 + nt * 8 + g) * KS_;
#pragma unroll
                    for (int kb = 0; kb < 8; kb++) {
                        const float2 bb = *(const float2*)(kp + kb * 8 + tq * 2);
                        uint32_t bfr[2];
                        bfr[0] = __float_as_uint(bb.x);
                        bfr[1] = __float_as_uint(bb.y);
                        mma8(sc[0][nt], qa[0][kb], bfr);
                        mma8(sc[1][nt], qa[1][kb], bfr);
                    }
                }

                // online softmax (base-2) per m16 sub-tile
#pragma unroll
                for (int mt2 = 0; mt2 < 2; mt2++) {
                    float smx_lo = -1e30f, smx_hi = -1e30f;
#pragma unroll
                    for (int nt = 0; nt < 8; nt++) {
                        smx_lo = fmaxf(smx_lo, fmaxf(sc[mt2][nt][0], sc[mt2][nt][1]));
                        smx_hi = fmaxf(smx_hi, fmaxf(sc[mt2][nt][2], sc[mt2][nt][3]));
                    }
                    smx_lo = fmaxf(smx_lo, __shfl_xor_sync(0xffffffffu, smx_lo, 1));
                    smx_lo = fmaxf(smx_lo, __shfl_xor_sync(0xffffffffu, smx_lo, 2));
                    smx_hi = fmaxf(smx_hi, __shfl_xor_sync(0xffffffffu, smx_hi, 1));
                    smx_hi = fmaxf(smx_hi, __shfl_xor_sync(0xffffffffu, smx_hi, 2));
                    const float mn_lo = fmaxf(mr[mt2][0], smx_lo);
                    const float mn_hi = fmaxf(mr[mt2][1], smx_hi);
                    const float corr_lo = ex2(mr[mt2][0] - mn_lo);
                    const float corr_hi = ex2(mr[mt2][1] - mn_hi);
                    mr[mt2][0] = mn_lo; mr[mt2][1] = mn_hi;
                    ls[mt2][0] *= corr_lo; ls[mt2][1] *= corr_hi;
#pragma unroll
                    for (int nt = 0; nt < 8; nt++) {
                        const float p0 = ex2(sc[mt2][nt][0] - mn_lo);
                        const float p1 = ex2(sc[mt2][nt][1] - mn_lo);
                        const float p2 = ex2(sc[mt2][nt][2] - mn_hi);
                        const float p3 = ex2(sc[mt2][nt][3] - mn_hi);
                        ls[mt2][0] += p0 + p1; ls[mt2][1] += p2 + p3;
                        sc[mt2][nt][0] = __uint_as_float(f2tf(p0));
                        sc[mt2][nt][1] = __uint_as_float(f2tf(p1));
                        sc[mt2][nt][2] = __uint_as_float(f2tf(p2));
                        sc[mt2][nt][3] = __uint_as_float(f2tf(p3));
                    }
#pragma unroll
                    for (int nv = 0; nv < 8; nv++) {
                        o[mt2][nv][0] *= corr_lo; o[mt2][nv][1] *= corr_lo;
                        o[mt2][nv][2] *= corr_hi; o[mt2][nv][3] *= corr_hi;
                    }
                }

                // O += P V (m32 x n64, k64): one V frag feeds 2 mma
#pragma unroll
                for (int kb = 0; kb < 8; kb++) {
                    uint32_t pa0[4], pa1[4];
                    pa0[0] = __float_as_uint(sc[0][kb][0]);
                    pa0[1] = __float_as_uint(sc[0][kb][2]);
                    pa0[2] = __float_as_uint(sc[0][kb][1]);
                    pa0[3] = __float_as_uint(sc[0][kb][3]);
                    pa1[0] = __float_as_uint(sc[1][kb][0]);
                    pa1[1] = __float_as_uint(sc[1][kb][2]);
                    pa1[2] = __float_as_uint(sc[1][kb][1]);
                    pa1[3] = __float_as_uint(sc[1][kb][3]);
#pragma unroll
                    for (int nv = 0; nv < 8; nv++) {
                        const float2 vv = *(const float2*)(Vs + (nv * 8 + g) * VS_ +
                                                           hk * 64 + kb * 8 + tq * 2);
                        uint32_t vb[2];
                        vb[0] = __float_as_uint(vv.x);
                        vb[1] = __float_as_uint(vv.y);
                        mma8(o[0][nv], pa0, vb);
                        mma8(o[1][nv], pa1, vb);
                    }
                }
            }
        }
        s ^= 1;
    }

    // finalize + write ctx (tf32-rounded, K-permuted for out-proj)
#pragma unroll
    for (int mt2 = 0; mt2 < 2; mt2++) {
        float ll = ls[mt2][0], lh = ls[mt2][1];
        ll += __shfl_xor_sync(0xffffffffu, ll, 1);
        ll += __shfl_xor_sync(0xffffffffu, ll, 2);
        lh += __shfl_xor_sync(0xffffffffu, lh, 1);
        lh += __shfl_xor_sync(0xffffffffu, lh, 2);
        const float il = 1.f / ll, ih = 1.f / lh;
        const int r0 = my_qc * CHUNK_ + wr0 + mt2 * 16 + g;
#pragma unroll
        for (int nv = 0; nv < 8; nv++) {
            const int col = h * HD_ + nv * 8 + 2 * tq;
            const int p0 = perm_idx(col), p1 = perm_idx(col + 1);
            float* c0 = ctx + ((size_t)b * L_ + r0) * D_;
            float* c1 = ctx + ((size_t)b * L_ + r0 + 8) * D_;
            c0[p0] = f2tff(o[mt2][nv][0] * il); c0[p1] = f2tff(o[mt2][nv][1] * il);
            c1[p0] = f2tff(o[mt2][nv][2] * ih); c1[p1] = f2tff(o[mt2][nv][3] * ih);
        }
    }
}

// ---------------------------------------------------------------------------
extern "C" void kernel_launch(void* const* d_in, const int* in_sizes, int n_in,
                              void* d_out, int out_size)
{
    const float* x    = (const float*)d_in[0];
    const float* Wqkv = (const float*)d_in[1];
    const float* bqkv = (const float*)d_in[2];
    const float* Wout = (const float*)d_in[3];
    const float* bout = (const float*)d_in[4];
    float* out = (float*)d_out;

    (void)in_sizes; (void)n_in; (void)out_size;

    cudaFuncSetAttribute(gemm_mma_kernel, cudaFuncAttributeMaxDynamicSharedMemorySize, GEMM_SMEM);
    cudaFuncSetAttribute(attn_mma_kernel, cudaFuncAttributeMaxDynamicSharedMemorySize, ATTN_SMEM);

    float *ctx_ptr, *xr, *wqkvr, *woutr;
    cudaGetSymbolAddress((void**)&ctx_ptr, g_ctx);
    cudaGetSymbolAddress((void**)&xr, g_xr);
    cudaGetSymbolAddress((void**)&wqkvr, g_wqkvr);
    cudaGetSymbolAddress((void**)&woutr, g_woutr);

    // 0. prep: round+permute x; transpose+round+permute weights
    {
        const int n8 = M_ROWS * D_ / 8;
        roundperm_kernel<<<(n8 + 255) / 256, 256>>>((const float4*)x, (float4*)xr, n8);
        dim3 blk(32, 8);
        transperm_kernel<<<dim3(QKV_N / 32, D_ / 32), blk>>>(Wqkv, wqkvr, D_, QKV_N);
        transperm_kernel<<<dim3(D_ / 32, D_ / 32), blk>>>(Wout, woutr, D_, D_);
    }
    // 1. QKV projection + scatter: q/k [bh][l][perm(d)], v [bh][d][l]
    {
        dim3 grid(QKV_N / 128, M_ROWS / 64);    // (24, 64) = 1536 CTAs
        gemm_mma_kernel<<<grid, 128, GEMM_SMEM>>>(xr, wqkvr, bqkv, nullptr,
                                                  M_ROWS, QKV_N, D_, 1);
    }
    // 2. Block-causal attention -> g_ctx (permuted, tf32-rounded)
    {
        attn_mma_kernel<<<8 * 32, 256, ATTN_SMEM>>>(ctx_ptr);
    }
    // 3. Output projection -> d_out
    {
        dim3 grid(D_ / 128, M_ROWS / 64);       // (8, 64) = 512 CTAs
        gemm_mma_kernel<<<grid, 128, GEMM_SMEM>>>(ctx_ptr, woutr, bout, out,
                                                  M_ROWS, D_, D_, 0);
    }
}

// round 14
// speedup vs baseline: 1.2185x; 1.0203x over previous
#include <cuda_runtime.h>
#include <cstdint>

// Problem constants
#define B_      2
#define L_      2048
#define D_      1024
#define H_      16
#define HD_     64
#define CHUNK_  128
#define M_ROWS  (B_ * L_)          // 4096
#define QKV_N   (3 * D_)           // 3072

// Scratch (device globals — no allocation allowed)
__device__ __align__(16) float g_q[(size_t)B_ * H_ * L_ * HD_];     // [bh][l][perm(d)]
__device__ __align__(16) float g_k[(size_t)B_ * H_ * L_ * HD_];     // [bh][l][perm(d)]
__device__ __align__(16) float g_v[(size_t)B_ * H_ * HD_ * L_];     // [bh][d][l]  (UNpermuted keys)
__device__ __align__(16) float g_ctx[(size_t)B_ * L_ * D_];         // [m][perm(c)]
__device__ __align__(16) float g_xr[(size_t)M_ROWS * D_];           // [m][perm(k)]
__device__ __align__(16) float g_wqkvr[(size_t)QKV_N * D_];         // [n][perm(k)] (transposed)
__device__ __align__(16) float g_woutr[(size_t)D_ * D_];            // [n][perm(k)] (transposed)

// ===========================================================================
// Helpers
// ===========================================================================
__device__ __forceinline__ uint32_t smem_u32(const void* p) {
    uint32_t a;
    asm("{ .reg .u64 t; cvta.to.shared.u64 t, %1; cvt.u32.u64 %0, t; }" : "=r"(a) : "l"(p));
    return a;
}
__device__ __forceinline__ uint32_t f2tf(float x) {
    uint32_t r;
    asm("cvt.rna.tf32.f32 %0, %1;" : "=r"(r) : "f"(x));
    return r;
}
__device__ __forceinline__ float f2tff(float x) { return __uint_as_float(f2tf(x)); }
__device__ __forceinline__ float ex2(float x) {
    float r;
    asm("ex2.approx.ftz.f32 %0, %1;" : "=f"(r) : "f"(x));
    return r;
}

// K-dim permutation: within each 8-group, b -> ((b&3)<<1)|(b>>2)
__device__ __forceinline__ int perm_idx(int i) {
    return (i & ~7) | ((i & 3) << 1) | ((i >> 2) & 1);
}

// m16n8k8 tf32 mma: D = A*B + D  (A row-major, B col-major)
__device__ __forceinline__ void mma8(float* c, const uint32_t* a, const uint32_t* b) {
    asm volatile(
        "mma.sync.aligned.m16n8k8.row.col.f32.tf32.tf32.f32 "
        "{%0,%1,%2,%3}, {%4,%5,%6,%7}, {%8,%9}, {%0,%1,%2,%3};"
        : "+f"(c[0]), "+f"(c[1]), "+f"(c[2]), "+f"(c[3])
        : "r"(a[0]), "r"(a[1]), "r"(a[2]), "r"(a[3]), "r"(b[0]), "r"(b[1]));
}

__device__ __forceinline__ void cp16(uint32_t dst, const void* src) {
    asm volatile("cp.async.cg.shared.global [%0], [%1], 16;" :: "r"(dst), "l"(src));
}
#define CP_COMMIT() asm volatile("cp.async.commit_group;" ::: "memory")
#define CP_WAIT0()  asm volatile("cp.async.wait_group 0;" ::: "memory")
#define CP_WAIT1()  asm volatile("cp.async.wait_group 1;" ::: "memory")

// ===========================================================================
// Fused prep kernel: one launch does x round+perm and both weight
// transpose+round+perm passes (branch on blockIdx range).
//   [0, 2048)        roundperm x      (n8 = 524288, 256 elem8/blk)
//   [2048, 5120)     transperm Wqkv   (grid 96 x 32)
//   [5120, 6144)     transperm Wout   (grid 32 x 32)
// ===========================================================================
__global__ __launch_bounds__(256) void prep_kernel(
    const float* __restrict__ x, const float* __restrict__ Wqkv,
    const float* __restrict__ Wout)
{
    __shared__ float tile[32][33];
    const int bid = blockIdx.x;
    if (bid < 2048) {
        const int i = bid * 256 + threadIdx.x;
        const float4* in = (const float4*)x;
        float4* out = (float4*)g_xr;
        const float4 a = in[2 * i], b = in[2 * i + 1];
        out[2 * i]     = make_float4(f2tff(a.x), f2tff(b.x), f2tff(a.y), f2tff(b.y));
        out[2 * i + 1] = make_float4(f2tff(a.z), f2tff(b.z), f2tff(a.w), f2tff(b.w));
        return;
    }
    const float* in;
    float* out;
    int N, bx, by;
    if (bid < 5120) {
        in = Wqkv; out = g_wqkvr; N = QKV_N;
        const int id = bid - 2048; bx = id % 96; by = id / 96;
    } else {
        in = Wout; out = g_woutr; N = D_;
        const int id = bid - 5120; bx = id % 32; by = id / 32;
    }
    const int K = D_;
    const int k0 = by * 32, n0 = bx * 32;
    const int tx = threadIdx.x & 31, ty = threadIdx.x >> 5;   // 32 x 8
#pragma unroll
    for (int i = 0; i < 4; i++)
        tile[ty + 8 * i][tx] = in[(size_t)(k0 + ty + 8 * i) * N + n0 + tx];
    __syncthreads();
    const int kp = k0 + perm_idx(tx);
#pragma unroll
    for (int i = 0; i < 4; i++)
        out[(size_t)(n0 + ty + 8 * i) * K + kp] = f2tff(tile[tx][ty + 8 * i]);
}

// ===========================================================================
// tf32 mma GEMM (R12 structure + software-pipelined fragment double buffer:
// load kb+1 fragments while issuing kb's mma burst).
// ===========================================================================
#define GSA       40
#define GA_STG_B  (64 * GSA * 4)          // 10240
#define GB_STG_B  (128 * 32 * 4)          // 16384
#define G_STG_B   (GA_STG_B + GB_STG_B)   // 26624
#define GEMM_SMEM (2 * G_STG_B)           // 53248

template<int S>
__device__ __forceinline__ void gemm_prefetch(
    uint32_t adst, uint32_t bdst, const char* asrc, const char* bsrc, int koff)
{
#pragma unroll
    for (int i = 0; i < 4; i++)
        cp16(adst + S * G_STG_B + i * (16 * GSA * 4), asrc + koff + i * (16 * D_ * 4));
#pragma unroll
    for (int i = 0; i < 8; i++)
        cp16(bdst + S * G_STG_B + i * (16 * 128), bsrc + koff + i * (16 * D_ * 4));
}

template<int S, int KB>
__device__ __forceinline__ void load_frags(
    uint32_t af[4][4], uint32_t bf[4][2],
    uint32_t abase, uint32_t bbase, const int* xo)
{
#pragma unroll
    for (int mt = 0; mt < 4; mt++) {
        float2 lo, hi;
        asm volatile("ld.shared.v2.f32 {%0,%1}, [%2];"
            : "=f"(lo.x), "=f"(lo.y)
            : "r"(abase + S * G_STG_B + mt * (16 * GSA * 4) + KB * 32));
        asm volatile("ld.shared.v2.f32 {%0,%1}, [%2];"
            : "=f"(hi.x), "=f"(hi.y)
            : "r"(abase + S * G_STG_B + mt * (16 * GSA * 4) + 8 * GSA * 4 + KB * 32));
        af[mt][0] = __float_as_uint(lo.x);
        af[mt][1] = __float_as_uint(hi.x);
        af[mt][2] = __float_as_uint(lo.y);
        af[mt][3] = __float_as_uint(hi.y);
    }
    const uint32_t bkb = bbase + (uint32_t)xo[KB];
#pragma unroll
    for (int nt = 0; nt < 4; nt++) {
        float2 bb;
        asm volatile("ld.shared.v2.f32 {%0,%1}, [%2];"
            : "=f"(bb.x), "=f"(bb.y)
            : "r"(bkb + S * G_STG_B + nt * (8 * 128)));
        bf[nt][0] = __float_as_uint(bb.x);
        bf[nt][1] = __float_as_uint(bb.y);
    }
}

__device__ __forceinline__ void mma_burst(
    float c[4][4][4], uint32_t af[4][4], uint32_t bf[4][2])
{
#pragma unroll
    for (int mt = 0; mt < 4; mt++)
#pragma unroll
        for (int nt = 0; nt < 4; nt++)
            mma8(c[mt][nt], af[mt], bf[nt]);
}

template<int S>
__device__ __forceinline__ void gemm_stage(
    float c[4][4][4], uint32_t abase, uint32_t bbase, const int* xo)
{
    uint32_t af[2][4][4], bf[2][4][2];
    load_frags<S, 0>(af[0], bf[0], abase, bbase, xo);
    load_frags<S, 1>(af[1], bf[1], abase, bbase, xo);
    mma_burst(c, af[0], bf[0]);
    load_frags<S, 2>(af[0], bf[0], abase, bbase, xo);
    mma_burst(c, af[1], bf[1]);
    load_frags<S, 3>(af[1], bf[1], abase, bbase, xo);
    mma_burst(c, af[0], bf[0]);
    mma_burst(c, af[1], bf[1]);
}

__global__ __launch_bounds__(128, 4) void gemm_mma_kernel(
    const float* __restrict__ A, const float* __restrict__ Bt,
    const float* __restrict__ bias, float* __restrict__ C,
    int M, int N, int K, int qkv_mode)
{
    extern __shared__ __align__(16) char sm[];
    const uint32_t sb = smem_u32(sm);
    const int tid = threadIdx.x, wid = tid >> 5, lane = tid & 31;
    const int g = lane >> 2, tq = lane & 3;
    const int bm = blockIdx.y * 64, bn = blockIdx.x * 128;
    const int wn = wid * 32;

    const int pr = tid >> 3, pc = tid & 7;
    const uint32_t adst = sb + pr * (GSA * 4) + pc * 16;
    const uint32_t bdst = sb + GA_STG_B + pr * 128 +
                          (uint32_t)((pc ^ ((pr & 3) << 1)) << 4);
    const char* asrc = (const char*)(A + (size_t)(bm + pr) * K) + pc * 16;
    const char* bsrc = (const char*)(Bt + (size_t)(bn + pr) * K) + pc * 16;

    const uint32_t abase = sb + (uint32_t)(g * (GSA * 4) + tq * 8);
    const uint32_t bbase = sb + GA_STG_B + (uint32_t)((wn + g) * 128 +
                           ((tq >> 1) << 4) + (tq & 1) * 8);
    int xo[4];
#pragma unroll
    for (int kb = 0; kb < 4; kb++) xo[kb] = (kb ^ (g & 3)) << 5;

    float c[4][4][4];
#pragma unroll
    for (int mt = 0; mt < 4; mt++)
#pragma unroll
        for (int nt = 0; nt < 4; nt++)
#pragma unroll
            for (int i = 0; i < 4; i++) c[mt][nt][i] = 0.f;

    const int KT = K >> 5;
    gemm_prefetch<0>(adst, bdst, asrc, bsrc, 0);   CP_COMMIT();
    gemm_prefetch<1>(adst, bdst, asrc, bsrc, 128); CP_COMMIT();

    for (int t = 0; t < KT; t += 2) {
        const int koff2 = (t + 2) * 128;
        CP_WAIT1();
        __syncthreads();
        gemm_stage<0>(c, abase, bbase, xo);
        __syncthreads();
        if (t + 2 < KT)
            gemm_prefetch<0>(adst, bdst, asrc, bsrc, koff2);
        CP_COMMIT();
        CP_WAIT1();
        __syncthreads();
        gemm_stage<1>(c, abase, bbase, xo);
        __syncthreads();
        if (t + 3 < KT)
            gemm_prefetch<1>(adst, bdst, asrc, bsrc, koff2 + 128);
        CP_COMMIT();
    }

#pragma unroll
    for (int mt = 0; mt < 4; mt++) {
#pragma unroll
        for (int nt = 0; nt < 4; nt++) {
            const int col = bn + wn + nt * 8 + 2 * tq;
            const float b0 = bias[col], b1 = bias[col + 1];
            const int r0 = bm + mt * 16 + g;
            const int r1 = r0 + 8;
            float v00 = c[mt][nt][0] + b0, v01 = c[mt][nt][1] + b1;
            float v10 = c[mt][nt][2] + b0, v11 = c[mt][nt][3] + b1;
            if (qkv_mode) {
                v00 = f2tff(v00); v01 = f2tff(v01);
                v10 = f2tff(v10); v11 = f2tff(v11);
                const int which = col >> 10;
                const int h  = (col >> 6) & 15;
                const int dd = col & 63;
                const int bh0 = (r0 >> 11) * H_ + h, l0 = r0 & 2047;
                const int bh1 = (r1 >> 11) * H_ + h, l1 = r1 & 2047;
                if (which == 2) {
                    g_v[((size_t)bh0 * HD_ + dd) * L_ + l0]     = v00;
                    g_v[((size_t)bh0 * HD_ + dd + 1) * L_ + l0] = v01;
                    g_v[((size_t)bh1 * HD_ + dd) * L_ + l1]     = v10;
                    g_v[((size_t)bh1 * HD_ + dd + 1) * L_ + l1] = v11;
                } else {
                    float* tgt = (which == 0) ? g_q : g_k;
                    const int pd0 = perm_idx(dd), pd1 = perm_idx(dd + 1);
                    float* d0 = tgt + ((size_t)bh0 * L_ + l0) * HD_;
                    float* d1 = tgt + ((size_t)bh1 * L_ + l1) * HD_;
                    d0[pd0] = v00; d0[pd1] = v01;
                    d1[pd0] = v10; d1[pd1] = v11;
                }
            } else {
                *(float2*)(C + (size_t)r0 * N + col) = make_float2(v00, v01);
                *(float2*)(C + (size_t)r1 * N + col) = make_float2(v10, v11);
            }
        }
    }
}

// ===========================================================================
// Block-causal flash attention (byte-identical to the proven R13 kernel).
// 256 threads, m32 warp tiles, two 64-key halves, K/V double-buffered.
// ===========================================================================
#define KS_ 72
#define VS_ 136
#define K_STAGE_B  (128 * KS_ * 4)           // 36864
#define V_STAGE_B  (HD_ * VS_ * 4)           // 34816
#define AT_VOFF    (2 * K_STAGE_B)           // 73728
#define ATTN_SMEM  (AT_VOFF + 2 * V_STAGE_B) // 143360

__device__ __forceinline__ void attn_prefetch_kv(
    uint32_t kdst, uint32_t vdst, const float* ksrc, const float* vsrc, int tid)
{
#pragma unroll
    for (int i = 0; i < 8; i++) {
        const int idx = tid + i * 256;
        const int r = idx >> 4, c = idx & 15;
        cp16(kdst + r * (KS_ * 4) + c * 16, ksrc + r * 64 + c * 4);
    }
#pragma unroll
    for (int i = 0; i < 8; i++) {
        const int idx = tid + i * 256;
        const int r = idx >> 5, c = idx & 31;
        cp16(vdst + r * (VS_ * 4) + c * 16, vsrc + (size_t)r * L_ + c * 4);
    }
}

__global__ __launch_bounds__(256, 1) void attn_mma_kernel(float* __restrict__ ctx)
{
    extern __shared__ __align__(16) char sm[];
    const uint32_t sb = smem_u32(sm);
    const int tid = threadIdx.x, wid = tid >> 5, lane = tid & 31;
    const int g = lane >> 2, tq = lane & 3;
    const int p  = 7 - ((int)blockIdx.x >> 5);
    const int bh = (int)blockIdx.x & 31;
    const int b = bh >> 4, h = bh & 15;
    const size_t head = (size_t)bh * L_ * HD_;
    const int half = wid >> 2;
    const int my_qc = 2 * p + half;
    const int qc_hi = 2 * p + 1;
    const int wr0 = (wid & 3) * 32;

    const float QSCALE = 0.125f * 1.4426950408889634f;
    uint32_t qa[2][8][4];
#pragma unroll
    for (int mt2 = 0; mt2 < 2; mt2++) {
        const float* qb = g_q + head + (size_t)(my_qc * CHUNK_ + wr0 + mt2 * 16) * HD_;
#pragma unroll
        for (int kb = 0; kb < 8; kb++) {
            const float2 lo = *(const float2*)(qb + g * 64 + kb * 8 + tq * 2);
            const float2 hi = *(const float2*)(qb + (g + 8) * 64 + kb * 8 + tq * 2);
            qa[mt2][kb][0] = __float_as_uint(lo.x * QSCALE);
            qa[mt2][kb][1] = __float_as_uint(hi.x * QSCALE);
            qa[mt2][kb][2] = __float_as_uint(lo.y * QSCALE);
            qa[mt2][kb][3] = __float_as_uint(hi.y * QSCALE);
        }
    }

    float o[2][8][4];
#pragma unroll
    for (int mt2 = 0; mt2 < 2; mt2++)
#pragma unroll
        for (int nv = 0; nv < 8; nv++)
#pragma unroll
            for (int i = 0; i < 4; i++) o[mt2][nv][i] = 0.f;
    float mr[2][2] = {{-1e30f, -1e30f}, {-1e30f, -1e30f}};
    float ls[2][2] = {{0.f, 0.f}, {0.f, 0.f}};

    attn_prefetch_kv(sb, sb + AT_VOFF, g_k + head, g_v + head, tid);
    CP_COMMIT();

    int s = 0;
    for (int kc = 0; kc <= qc_hi; kc++) {
        CP_WAIT0();
        __syncthreads();

        if (kc < qc_hi)
            attn_prefetch_kv(sb + (uint32_t)(s ^ 1) * K_STAGE_B,
                             sb + AT_VOFF + (uint32_t)(s ^ 1) * V_STAGE_B,
                             g_k + head + (size_t)(kc + 1) * CHUNK_ * HD_,
                             g_v + head + (size_t)(kc + 1) * CHUNK_, tid);
        CP_COMMIT();

        if (kc <= my_qc) {
            const float* Ks = (const float*)(sm + (size_t)s * K_STAGE_B);
            const float* Vs = (const float*)(sm + AT_VOFF + (size_t)s * V_STAGE_B);

#pragma unroll
            for (int hk = 0; hk < 2; hk++) {
                float sc[2][8][4];
#pragma unroll
                for (int nt = 0; nt < 8; nt++) {
                    sc[0][nt][0] = sc[0][nt][1] = sc[0][nt][2] = sc[0][nt][3] = 0.f;
                    sc[1][nt][0] = sc[1][nt][1] = sc[1][nt][2] = sc[1][nt][3] = 0.f;
                    const float* kp = Ks + (hk * 64 + nt * 8 + g) * KS_;
#pragma unroll
                    for (int kb = 0; kb < 8; kb++) {
                        const float2 bb = *(const float2*)(kp + kb * 8 + tq * 2);
                        uint32_t bfr[2];
                        bfr[0] = __float_as_uint(bb.x);
                        bfr[1] = __float_as_uint(bb.y);
                        mma8(sc[0][nt], qa[0][kb], bfr);
                        mma8(sc[1][nt], qa[1][kb], bfr);
                    }
                }

#pragma unroll
                for (int mt2 = 0; mt2 < 2; mt2++) {
                    float smx_lo = -1e30f, smx_hi = -1e30f;
#pragma unroll
                    for (int nt = 0; nt < 8; nt++) {
                        smx_lo = fmaxf(smx_lo, fmaxf(sc[mt2][nt][0], sc[mt2][nt][1]));
                        smx_hi = fmaxf(smx_hi, fmaxf(sc[mt2][nt][2], sc[mt2][nt][3]));
                    }
                    smx_lo = fmaxf(smx_lo, __shfl_xor_sync(0xffffffffu, smx_lo, 1));
                    smx_lo = fmaxf(smx_lo, __shfl_xor_sync(0xffffffffu, smx_lo, 2));
                    smx_hi = fmaxf(smx_hi, __shfl_xor_sync(0xffffffffu, smx_hi, 1));
                    smx_hi = fmaxf(smx_hi, __shfl_xor_sync(0xffffffffu, smx_hi, 2));
                    const float mn_lo = fmaxf(mr[mt2][0], smx_lo);
                    const float mn_hi = fmaxf(mr[mt2][1], smx_hi);
                    const float corr_lo = ex2(mr[mt2][0] - mn_lo);
                    const float corr_hi = ex2(mr[mt2][1] - mn_hi);
                    mr[mt2][0] = mn_lo; mr[mt2][1] = mn_hi;
                    ls[mt2][0] *= corr_lo; ls[mt2][1] *= corr_hi;
#pragma unroll
                    for (int nt = 0; nt < 8; nt++) {
                        const float p0 = ex2(sc[mt2][nt][0] - mn_lo);
                        const float p1 = ex2(sc[mt2][nt][1] - mn_lo);
                        const float p2 = ex2(sc[mt2][nt][2] - mn_hi);
                        const float p3 = ex2(sc[mt2][nt][3] - mn_hi);
                        ls[mt2][0] += p0 + p1; ls[mt2][1] += p2 + p3;
                        sc[mt2][nt][0] = __uint_as_float(f2tf(p0));
                        sc[mt2][nt][1] = __uint_as_float(f2tf(p1));
                        sc[mt2][nt][2] = __uint_as_float(f2tf(p2));
                        sc[mt2][nt][3] = __uint_as_float(f2tf(p3));
                    }
#pragma unroll
                    for (int nv = 0; nv < 8; nv++) {
                        o[mt2][nv][0] *= corr_lo; o[mt2][nv][1] *= corr_lo;
                        o[mt2][nv][2] *= corr_hi; o[mt2][nv][3] *= corr_hi;
                    }
                }

#pragma unroll
                for (int kb = 0; kb < 8; kb++) {
                    uint32_t pa0[4], pa1[4];
                    pa0[0] = __float_as_uint(sc[0][kb][0]);
                    pa0[1] = __float_as_uint(sc[0][kb][2]);
                    pa0[2] = __float_as_uint(sc[0][kb][1]);
                    pa0[3] = __float_as_uint(sc[0][kb][3]);
                    pa1[0] = __float_as_uint(sc[1][kb][0]);
                    pa1[1] = __float_as_uint(sc[1][kb][2]);
                    pa1[2] = __float_as_uint(sc[1][kb][1]);
                    pa1[3] = __float_as_uint(sc[1][kb][3]);
#pragma unroll
                    for (int nv = 0; nv < 8; nv++) {
                        const float2 vv = *(const float2*)(Vs + (nv * 8 + g) * VS_ +
                                                           hk * 64 + kb * 8 + tq * 2);
                        uint32_t vb[2];
                        vb[0] = __float_as_uint(vv.x);
                        vb[1] = __float_as_uint(vv.y);
                        mma8(o[0][nv], pa0, vb);
                        mma8(o[1][nv], pa1, vb);
                    }
                }
            }
        }
        s ^= 1;
    }

#pragma unroll
    for (int mt2 = 0; mt2 < 2; mt2++) {
        float ll = ls[mt2][0], lh = ls[mt2][1];
        ll += __shfl_xor_sync(0xffffffffu, ll, 1);
        ll += __shfl_xor_sync(0xffffffffu, ll, 2);
        lh += __shfl_xor_sync(0xffffffffu, lh, 1);
        lh += __shfl_xor_sync(0xffffffffu, lh, 2);
        const float il = 1.f / ll, ih = 1.f / lh;
        const int r0 = my_qc * CHUNK_ + wr0 + mt2 * 16 + g;
#pragma unroll
        for (int nv = 0; nv < 8; nv++) {
            const int col = h * HD_ + nv * 8 + 2 * tq;
            const int p0 = perm_idx(col), p1 = perm_idx(col + 1);
            float* c0 = ctx + ((size_t)b * L_ + r0) * D_;
            float* c1 = ctx + ((size_t)b * L_ + r0 + 8) * D_;
            c0[p0] = f2tff(o[mt2][nv][0] * il); c0[p1] = f2tff(o[mt2][nv][1] * il);
            c1[p0] = f2tff(o[mt2][nv][2] * ih); c1[p1] = f2tff(o[mt2][nv][3] * ih);
        }
    }
}

// ---------------------------------------------------------------------------
extern "C" void kernel_launch(void* const* d_in, const int* in_sizes, int n_in,
                              void* d_out, int out_size)
{
    const float* x    = (const float*)d_in[0];
    const float* Wqkv = (const float*)d_in[1];
    const float* bqkv = (const float*)d_in[2];
    const float* Wout = (const float*)d_in[3];
    const float* bout = (const float*)d_in[4];
    float* out = (float*)d_out;

    (void)in_sizes; (void)n_in; (void)out_size;

    cudaFuncSetAttribute(gemm_mma_kernel, cudaFuncAttributeMaxDynamicSharedMemorySize, GEMM_SMEM);
    cudaFuncSetAttribute(attn_mma_kernel, cudaFuncAttributeMaxDynamicSharedMemorySize, ATTN_SMEM);

    float *ctx_ptr, *xr, *wqkvr, *woutr;
    cudaGetSymbolAddress((void**)&ctx_ptr, g_ctx);
    cudaGetSymbolAddress((void**)&xr, g_xr);
    cudaGetSymbolAddress((void**)&wqkvr, g_wqkvr);
    cudaGetSymbolAddress((void**)&woutr, g_woutr);

    // 0. fused prep: round+permute x; transpose+round+permute both weights
    prep_kernel<<<6144, 256>>>(x, Wqkv, Wout);

    // 1. QKV projection + scatter: q/k [bh][l][perm(d)], v [bh][d][l]
    {
        dim3 grid(QKV_N / 128, M_ROWS / 64);    // (24, 64) = 1536 CTAs
        gemm_mma_kernel<<<grid, 128, GEMM_SMEM>>>(xr, wqkvr, bqkv, nullptr,
                                                  M_ROWS, QKV_N, D_, 1);
    }
    // 2. Block-causal attention -> g_ctx (permuted, tf32-rounded)
    {
        attn_mma_kernel<<<8 * 32, 256, ATTN_SMEM>>>(ctx_ptr);
    }
    // 3. Output projection -> d_out
    {
        dim3 grid(D_ / 128, M_ROWS / 64);       // (8, 64) = 512 CTAs
        gemm_mma_kernel<<<grid, 128, GEMM_SMEM>>>(ctx_ptr, woutr, bout, out,
                                                  M_ROWS, D_, D_, 0);
    }
}